// round 4
// baseline (speedup 1.0000x reference)
#include <cuda_runtime.h>
#include <cstdint>

// Problem constants
#define BATCH 512
#define SEQ 512
#define FD 128          // filler dim
#define RD 64           // role dim
#define FW 768          // final width
#define KFLAT (FD*RD)   // 8192
#define KSPLIT 8
#define NUM_FILLERS 50257
#define NUM_ROLES 512

// Scratch (device globals: allocation-free per harness rules)
__device__ float g_outer[(size_t)BATCH * KFLAT];         // 16.8 MB
__device__ float g_partial[(size_t)KSPLIT * BATCH * FW]; // 12.6 MB
__device__ int   g_flags[2];  // [0]=swap(a<->b), [1]=int64 indices

// ---------------------------------------------------------------------------
// Kernel 0: disambiguate the two 262144-element index arrays + detect dtype.
// ---------------------------------------------------------------------------
__global__ void detect_kernel(const int* __restrict__ a, const int* __restrict__ b)
{
    if (threadIdx.x != 0 || blockIdx.x != 0) return;
    int odd_nonzero = 0;
#pragma unroll 8
    for (int i = 0; i < 256; i++) odd_nonzero |= a[2 * i + 1];
    const int is64 = (odd_nonzero == 0) ? 1 : 0;
    const int s = is64 ? 2 : 1;
    int amax = 0, bmax = 0;
#pragma unroll 8
    for (int i = 0; i < 256; i++) {
        amax = max(amax, a[i * s]);
        bmax = max(bmax, b[i * s]);
    }
    g_flags[0] = (amax < NUM_ROLES && bmax >= NUM_ROLES) ? 1 : 0;
    g_flags[1] = is64;
}

// ---------------------------------------------------------------------------
// Kernel 1: per-batch outer-product accumulation
//   outer[b][f][r] = sum_s ftab[fillers[b][s]][f] * rtab[roles[b][s]][r]
// grid = 512 (one CTA per batch), 128 threads, 8x8 register tile over 128x64.
// ---------------------------------------------------------------------------
__global__ __launch_bounds__(128) void outer_kernel(
    const int* __restrict__ ia,
    const int* __restrict__ ib,
    const float* __restrict__ ftab,
    const float* __restrict__ rtab)
{
    __shared__ float fe[32][FD];   // 16 KB
    __shared__ float re[32][RD];   // 8 KB
    __shared__ int sf[32];
    __shared__ int sr[32];

    const int b   = blockIdx.x;
    const int tid = threadIdx.x;
    const int m0  = (tid >> 3) * 8;   // 16 groups * 8 = 128 (filler dim)
    const int n0  = (tid & 7) * 8;    // 8 groups * 8 = 64  (role dim)

    const int swap = g_flags[0];
    const int strd = g_flags[1] ? 2 : 1;
    const int* __restrict__ fidx = swap ? ib : ia;
    const int* __restrict__ ridx = swap ? ia : ib;

    float acc[8][8];
#pragma unroll
    for (int i = 0; i < 8; i++)
#pragma unroll
        for (int j = 0; j < 8; j++) acc[i][j] = 0.f;

    for (int k0 = 0; k0 < SEQ; k0 += 32) {
        if (tid < 32) {
            size_t e = (size_t)b * SEQ + k0 + tid;
            int f = fidx[e * strd];
            int r = ridx[e * strd];
            sf[tid] = min(max(f, 0), NUM_FILLERS - 1);
            sr[tid] = min(max(r, 0), NUM_ROLES - 1);
        }
        __syncthreads();

        {   // fe tile: 32 rows x 32 float4; each warp loads full 512B rows
            int kk0 = tid >> 5;
            int d4  = tid & 31;
#pragma unroll
            for (int it = 0; it < 8; it++) {
                int kk = kk0 + it * 4;
                float4 v = ((const float4*)(ftab + (size_t)sf[kk] * FD))[d4];
                ((float4*)fe[kk])[d4] = v;
            }
        }
        {   // re tile: 32 rows x 16 float4
            int kk0 = tid >> 4;
            int d4  = tid & 15;
#pragma unroll
            for (int it = 0; it < 4; it++) {
                int kk = kk0 + it * 8;
                float4 v = ((const float4*)(rtab + (size_t)sr[kk] * RD))[d4];
                ((float4*)re[kk])[d4] = v;
            }
        }
        __syncthreads();

#pragma unroll
        for (int k = 0; k < 32; k++) {
            float a[8], c[8];
            *(float4*)&a[0] = *(const float4*)&fe[k][m0];
            *(float4*)&a[4] = *(const float4*)&fe[k][m0 + 4];
            *(float4*)&c[0] = *(const float4*)&re[k][n0];
            *(float4*)&c[4] = *(const float4*)&re[k][n0 + 4];
#pragma unroll
            for (int i = 0; i < 8; i++)
#pragma unroll
                for (int j = 0; j < 8; j++)
                    acc[i][j] = fmaf(a[i], c[j], acc[i][j]);
        }
        __syncthreads();
    }

    float* outp = g_outer + (size_t)b * KFLAT;
#pragma unroll
    for (int i = 0; i < 8; i++) {
#pragma unroll
        for (int j = 0; j < 8; j += 4) {
            float4 v = make_float4(acc[i][j], acc[i][j+1], acc[i][j+2], acc[i][j+3]);
            *(float4*)&outp[(size_t)(m0 + i) * RD + n0 + j] = v;
        }
    }
}

// ---------------------------------------------------------------------------
// Kernel 2: split-K GEMM, CTA tile M=128 x N=64, K-tile 32.
//   partial[ks][m][n] = sum_{k in chunk} g_outer[m][k] * W[n][k]
// grid = (BATCH/128=4, FW/64=12, KSPLIT=8), block = 128 threads, 8x8/thread.
// As stride 132 floats (528B rows, 16B aligned); Bs stride 68 (272B rows).
// ---------------------------------------------------------------------------
#define ASTRIDE 132
#define BSTRIDE 68
__global__ __launch_bounds__(128) void gemm2_kernel(const float* __restrict__ W)
{
    __shared__ float As[32][ASTRIDE];  // 16.9 KB
    __shared__ float Bs[32][BSTRIDE];  // 8.7 KB

    const int tid   = threadIdx.x;
    const int mtile = blockIdx.x;
    const int ntile = blockIdx.y;
    const int ks    = blockIdx.z;
    const int m0    = (tid >> 3) * 8;  // 0..120 over 128-row M tile
    const int n0    = (tid & 7) * 8;   // 0..56  over 64-col N tile

    const float* A  = g_outer + (size_t)(mtile * 128) * KFLAT;
    const float* Bw = W       + (size_t)(ntile * 64) * KFLAT;
    const int kbase = ks * (KFLAT / KSPLIT);   // 1024-long chunk

    float acc[8][8];
#pragma unroll
    for (int i = 0; i < 8; i++)
#pragma unroll
        for (int j = 0; j < 8; j++) acc[i][j] = 0.f;

    for (int k0 = kbase; k0 < kbase + KFLAT / KSPLIT; k0 += 32) {
        // A tile: 128 rows x 8 float4 = 1024 float4 / 128 threads = 8 each
#pragma unroll
        for (int it = 0; it < 8; it++) {
            int id = it * 128 + tid;
            int m  = id >> 3;          // 0..127
            int k4 = id & 7;           // 0..7
            float4 v = *(const float4*)(A + (size_t)m * KFLAT + k0 + k4 * 4);
            As[k4 * 4 + 0][m] = v.x;
            As[k4 * 4 + 1][m] = v.y;
            As[k4 * 4 + 2][m] = v.z;
            As[k4 * 4 + 3][m] = v.w;
        }
        // B tile: 64 rows x 8 float4 = 512 float4 / 128 threads = 4 each
#pragma unroll
        for (int it = 0; it < 4; it++) {
            int id = it * 128 + tid;
            int n  = id >> 3;          // 0..63
            int k4 = id & 7;
            float4 v = *(const float4*)(Bw + (size_t)n * KFLAT + k0 + k4 * 4);
            Bs[k4 * 4 + 0][n] = v.x;
            Bs[k4 * 4 + 1][n] = v.y;
            Bs[k4 * 4 + 2][n] = v.z;
            Bs[k4 * 4 + 3][n] = v.w;
        }
        __syncthreads();

#pragma unroll
        for (int k = 0; k < 32; k++) {
            float a[8], c[8];
            *(float4*)&a[0] = *(const float4*)&As[k][m0];
            *(float4*)&a[4] = *(const float4*)&As[k][m0 + 4];
            *(float4*)&c[0] = *(const float4*)&Bs[k][n0];
            *(float4*)&c[4] = *(const float4*)&Bs[k][n0 + 4];
#pragma unroll
            for (int i = 0; i < 8; i++)
#pragma unroll
                for (int j = 0; j < 8; j++)
                    acc[i][j] = fmaf(a[i], c[j], acc[i][j]);
        }
        __syncthreads();
    }

    // partial[ks][mtile*128 + m][ntile*64 + n]
    float* P = g_partial + ((size_t)ks * BATCH + mtile * 128) * FW + ntile * 64;
#pragma unroll
    for (int i = 0; i < 8; i++) {
#pragma unroll
        for (int j = 0; j < 8; j += 4) {
            float4 v = make_float4(acc[i][j], acc[i][j+1], acc[i][j+2], acc[i][j+3]);
            *(float4*)&P[(size_t)(m0 + i) * FW + n0 + j] = v;
        }
    }
}

// ---------------------------------------------------------------------------
// Kernel 3: reduce split-K partials + bias -> out[1][B][FW]
// ---------------------------------------------------------------------------
__global__ void reduce_kernel(const float* __restrict__ bias, float* __restrict__ out)
{
    int idx = blockIdx.x * 256 + threadIdx.x;
    if (idx < BATCH * FW) {
        int n = idx % FW;
        float s = bias[n];
#pragma unroll
        for (int ks = 0; ks < KSPLIT; ks++)
            s += g_partial[(size_t)ks * BATCH * FW + idx];
        out[idx] = s;
    }
}

// ---------------------------------------------------------------------------
// Identify inputs by element count (robust to metadata ordering):
//   262144 x2 -> fillers/roles (device-disambiguated)
//   6432896 -> filler_table, 32768 -> role_table, 6291456 -> W_last, 768 -> b_last
// ---------------------------------------------------------------------------
extern "C" void kernel_launch(void* const* d_in, const int* in_sizes, int n_in,
                              void* d_out, int out_size)
{
    const void* idx_arr[2] = {nullptr, nullptr};
    int n_idx = 0;
    const float* ftab = nullptr;
    const float* rtab = nullptr;
    const float* W    = nullptr;
    const float* bias = nullptr;

    for (int i = 0; i < n_in; i++) {
        switch (in_sizes[i]) {
            case BATCH * SEQ:
                if (n_idx < 2) idx_arr[n_idx++] = d_in[i];
                break;
            case NUM_FILLERS * FD: ftab = (const float*)d_in[i]; break;
            case NUM_ROLES * RD:   rtab = (const float*)d_in[i]; break;
            case FW * KFLAT:       W    = (const float*)d_in[i]; break;
            case FW:               bias = (const float*)d_in[i]; break;
            default: break;
        }
    }

    const int* ia = (const int*)idx_arr[0];
    const int* ib = (const int*)idx_arr[1];
    float* out = (float*)d_out;

    detect_kernel<<<1, 1>>>(ia, ib);
    outer_kernel<<<BATCH, 128>>>(ia, ib, ftab, rtab);

    dim3 grid2(BATCH / 128, FW / 64, KSPLIT);
    gemm2_kernel<<<grid2, 128>>>(W);

    reduce_kernel<<<(BATCH * FW + 255) / 256, 256>>>(bias, out);
}

// round 5
// speedup vs baseline: 1.0546x; 1.0546x over previous
#include <cuda_runtime.h>
#include <cstdint>

// Problem constants
#define BATCH 512
#define SEQ 512
#define FD 128          // filler dim
#define RD 64           // role dim
#define FW 768          // final width
#define KFLAT (FD*RD)   // 8192
#define KSPLIT 8
#define NUM_FILLERS 50257
#define NUM_ROLES 512

typedef unsigned long long u64;

// Scratch (device globals: allocation-free per harness rules)
__device__ float g_outer[(size_t)BATCH * KFLAT];         // 16.8 MB
__device__ float g_partial[(size_t)KSPLIT * BATCH * FW]; // 12.6 MB
__device__ int   g_flags[2];  // [0]=swap(a<->b), [1]=int64 indices

// ---- packed f32x2 helpers (sm_100a) ---------------------------------------
__device__ __forceinline__ u64 ffma2(u64 a, u64 b, u64 c) {
    u64 d;
    asm("fma.rn.f32x2 %0, %1, %2, %3;" : "=l"(d) : "l"(a), "l"(b), "l"(c));
    return d;
}
__device__ __forceinline__ u64 splat2(float x) {
    u64 r;
    asm("mov.b64 %0, {%1, %1};" : "=l"(r) : "f"(x));
    return r;
}
__device__ __forceinline__ void unpack2(u64 v, float& lo, float& hi) {
    asm("mov.b64 {%0, %1}, %2;" : "=f"(lo), "=f"(hi) : "l"(v));
}

// ---------------------------------------------------------------------------
// Kernel 0: disambiguate the two 262144-element index arrays + detect dtype.
// ---------------------------------------------------------------------------
__global__ void detect_kernel(const int* __restrict__ a, const int* __restrict__ b)
{
    if (threadIdx.x != 0 || blockIdx.x != 0) return;
    int odd_nonzero = 0;
#pragma unroll 8
    for (int i = 0; i < 256; i++) odd_nonzero |= a[2 * i + 1];
    const int is64 = (odd_nonzero == 0) ? 1 : 0;
    const int s = is64 ? 2 : 1;
    int amax = 0, bmax = 0;
#pragma unroll 8
    for (int i = 0; i < 256; i++) {
        amax = max(amax, a[i * s]);
        bmax = max(bmax, b[i * s]);
    }
    g_flags[0] = (amax < NUM_ROLES && bmax >= NUM_ROLES) ? 1 : 0;
    g_flags[1] = is64;
}

// ---------------------------------------------------------------------------
// Kernel 1: per-batch outer-product accumulation (FFMA2 inner loop)
//   outer[b][f][r] = sum_s ftab[fillers[b][s]][f] * rtab[roles[b][s]][r]
// grid = 512, 128 threads, 8(m)x8(n) register tile; acc packed along m.
// ---------------------------------------------------------------------------
__global__ __launch_bounds__(128) void outer_kernel(
    const int* __restrict__ ia,
    const int* __restrict__ ib,
    const float* __restrict__ ftab,
    const float* __restrict__ rtab)
{
    __shared__ float fe[32][FD];   // 16 KB
    __shared__ float re[32][RD];   // 8 KB
    __shared__ int sf[32];
    __shared__ int sr[32];

    const int b   = blockIdx.x;
    const int tid = threadIdx.x;
    const int m0  = (tid >> 3) * 8;   // 16 groups * 8 = 128 (filler dim)
    const int n0  = (tid & 7) * 8;    // 8 groups * 8 = 64  (role dim)

    const int swap = g_flags[0];
    const int strd = g_flags[1] ? 2 : 1;
    const int* __restrict__ fidx = swap ? ib : ia;
    const int* __restrict__ ridx = swap ? ia : ib;

    // acc2[i2][j] packs rows (2*i2, 2*i2+1) for column j
    u64 acc2[4][8];
#pragma unroll
    for (int i = 0; i < 4; i++)
#pragma unroll
        for (int j = 0; j < 8; j++) acc2[i][j] = 0ull;

    for (int k0 = 0; k0 < SEQ; k0 += 32) {
        if (tid < 32) {
            size_t e = (size_t)b * SEQ + k0 + tid;
            int f = fidx[e * strd];
            int r = ridx[e * strd];
            sf[tid] = min(max(f, 0), NUM_FILLERS - 1);
            sr[tid] = min(max(r, 0), NUM_ROLES - 1);
        }
        __syncthreads();

        {   // fe tile: 32 rows x 32 float4; each warp loads full 512B rows
            int kk0 = tid >> 5;
            int d4  = tid & 31;
#pragma unroll
            for (int it = 0; it < 8; it++) {
                int kk = kk0 + it * 4;
                float4 v = ((const float4*)(ftab + (size_t)sf[kk] * FD))[d4];
                ((float4*)fe[kk])[d4] = v;
            }
        }
        {   // re tile: 32 rows x 16 float4
            int kk0 = tid >> 4;
            int d4  = tid & 15;
#pragma unroll
            for (int it = 0; it < 4; it++) {
                int kk = kk0 + it * 8;
                float4 v = ((const float4*)(rtab + (size_t)sr[kk] * RD))[d4];
                ((float4*)re[kk])[d4] = v;
            }
        }
        __syncthreads();

#pragma unroll
        for (int k = 0; k < 32; k++) {
            // a packed pairs straight from smem (m contiguous)
            ulonglong2 p0 = *(const ulonglong2*)&fe[k][m0];
            ulonglong2 p1 = *(const ulonglong2*)&fe[k][m0 + 4];
            u64 a2[4] = {p0.x, p0.y, p1.x, p1.y};
            float c[8];
            *(float4*)&c[0] = *(const float4*)&re[k][n0];
            *(float4*)&c[4] = *(const float4*)&re[k][n0 + 4];
            u64 c2[8];
#pragma unroll
            for (int j = 0; j < 8; j++) c2[j] = splat2(c[j]);
#pragma unroll
            for (int i = 0; i < 4; i++)
#pragma unroll
                for (int j = 0; j < 8; j++)
                    acc2[i][j] = ffma2(a2[i], c2[j], acc2[i][j]);
        }
        __syncthreads();
    }

    // unpack + store: row m0+2*i2 (lo) and m0+2*i2+1 (hi)
    float* outp = g_outer + (size_t)b * KFLAT;
#pragma unroll
    for (int i2 = 0; i2 < 4; i2++) {
        float lo[8], hi[8];
#pragma unroll
        for (int j = 0; j < 8; j++) unpack2(acc2[i2][j], lo[j], hi[j]);
        float* r0 = outp + (size_t)(m0 + 2 * i2) * RD + n0;
        float* r1 = r0 + RD;
        *(float4*)&r0[0] = make_float4(lo[0], lo[1], lo[2], lo[3]);
        *(float4*)&r0[4] = make_float4(lo[4], lo[5], lo[6], lo[7]);
        *(float4*)&r1[0] = make_float4(hi[0], hi[1], hi[2], hi[3]);
        *(float4*)&r1[4] = make_float4(hi[4], hi[5], hi[6], hi[7]);
    }
}

// ---------------------------------------------------------------------------
// Kernel 2: split-K GEMM, CTA tile M=128 x N=64, K-tile 32 (FFMA2 inner loop)
//   partial[ks][m][n] = sum_{k in chunk} g_outer[m][k] * W[n][k]
// grid = (4, 12, 8), block = 128 threads, 8x8/thread packed along m.
// ---------------------------------------------------------------------------
#define ASTRIDE 132
#define BSTRIDE 68
__global__ __launch_bounds__(128) void gemm2_kernel(const float* __restrict__ W)
{
    __shared__ float As[32][ASTRIDE];  // 16.9 KB
    __shared__ float Bs[32][BSTRIDE];  // 8.7 KB

    const int tid   = threadIdx.x;
    const int mtile = blockIdx.x;
    const int ntile = blockIdx.y;
    const int ks    = blockIdx.z;
    const int m0    = (tid >> 3) * 8;
    const int n0    = (tid & 7) * 8;

    const float* A  = g_outer + (size_t)(mtile * 128) * KFLAT;
    const float* Bw = W       + (size_t)(ntile * 64) * KFLAT;
    const int kbase = ks * (KFLAT / KSPLIT);

    u64 acc2[4][8];
#pragma unroll
    for (int i = 0; i < 4; i++)
#pragma unroll
        for (int j = 0; j < 8; j++) acc2[i][j] = 0ull;

    for (int k0 = kbase; k0 < kbase + KFLAT / KSPLIT; k0 += 32) {
        // A tile: 128 rows x 8 float4 = 1024 / 128 threads = 8 each
#pragma unroll
        for (int it = 0; it < 8; it++) {
            int id = it * 128 + tid;
            int m  = id >> 3;
            int k4 = id & 7;
            float4 v = *(const float4*)(A + (size_t)m * KFLAT + k0 + k4 * 4);
            As[k4 * 4 + 0][m] = v.x;
            As[k4 * 4 + 1][m] = v.y;
            As[k4 * 4 + 2][m] = v.z;
            As[k4 * 4 + 3][m] = v.w;
        }
        // B tile: 64 rows x 8 float4 = 512 / 128 threads = 4 each
#pragma unroll
        for (int it = 0; it < 4; it++) {
            int id = it * 128 + tid;
            int n  = id >> 3;
            int k4 = id & 7;
            float4 v = *(const float4*)(Bw + (size_t)n * KFLAT + k0 + k4 * 4);
            Bs[k4 * 4 + 0][n] = v.x;
            Bs[k4 * 4 + 1][n] = v.y;
            Bs[k4 * 4 + 2][n] = v.z;
            Bs[k4 * 4 + 3][n] = v.w;
        }
        __syncthreads();

#pragma unroll
        for (int k = 0; k < 32; k++) {
            ulonglong2 p0 = *(const ulonglong2*)&As[k][m0];
            ulonglong2 p1 = *(const ulonglong2*)&As[k][m0 + 4];
            u64 a2[4] = {p0.x, p0.y, p1.x, p1.y};
            float c[8];
            *(float4*)&c[0] = *(const float4*)&Bs[k][n0];
            *(float4*)&c[4] = *(const float4*)&Bs[k][n0 + 4];
            u64 c2[8];
#pragma unroll
            for (int j = 0; j < 8; j++) c2[j] = splat2(c[j]);
#pragma unroll
            for (int i = 0; i < 4; i++)
#pragma unroll
                for (int j = 0; j < 8; j++)
                    acc2[i][j] = ffma2(a2[i], c2[j], acc2[i][j]);
        }
        __syncthreads();
    }

    float* P = g_partial + ((size_t)ks * BATCH + mtile * 128) * FW + ntile * 64;
#pragma unroll
    for (int i2 = 0; i2 < 4; i2++) {
        float lo[8], hi[8];
#pragma unroll
        for (int j = 0; j < 8; j++) unpack2(acc2[i2][j], lo[j], hi[j]);
        float* r0 = P + (size_t)(m0 + 2 * i2) * FW + n0;
        float* r1 = r0 + FW;
        *(float4*)&r0[0] = make_float4(lo[0], lo[1], lo[2], lo[3]);
        *(float4*)&r0[4] = make_float4(lo[4], lo[5], lo[6], lo[7]);
        *(float4*)&r1[0] = make_float4(hi[0], hi[1], hi[2], hi[3]);
        *(float4*)&r1[4] = make_float4(hi[4], hi[5], hi[6], hi[7]);
    }
}

// ---------------------------------------------------------------------------
// Kernel 3: reduce split-K partials + bias -> out[1][B][FW]
// ---------------------------------------------------------------------------
__global__ void reduce_kernel(const float* __restrict__ bias, float* __restrict__ out)
{
    int idx = blockIdx.x * 256 + threadIdx.x;
    if (idx < BATCH * FW) {
        int n = idx % FW;
        float s = bias[n];
#pragma unroll
        for (int ks = 0; ks < KSPLIT; ks++)
            s += g_partial[(size_t)ks * BATCH * FW + idx];
        out[idx] = s;
    }
}

// ---------------------------------------------------------------------------
// Identify inputs by element count (robust to metadata ordering).
// ---------------------------------------------------------------------------
extern "C" void kernel_launch(void* const* d_in, const int* in_sizes, int n_in,
                              void* d_out, int out_size)
{
    const void* idx_arr[2] = {nullptr, nullptr};
    int n_idx = 0;
    const float* ftab = nullptr;
    const float* rtab = nullptr;
    const float* W    = nullptr;
    const float* bias = nullptr;

    for (int i = 0; i < n_in; i++) {
        switch (in_sizes[i]) {
            case BATCH * SEQ:
                if (n_idx < 2) idx_arr[n_idx++] = d_in[i];
                break;
            case NUM_FILLERS * FD: ftab = (const float*)d_in[i]; break;
            case NUM_ROLES * RD:   rtab = (const float*)d_in[i]; break;
            case FW * KFLAT:       W    = (const float*)d_in[i]; break;
            case FW:               bias = (const float*)d_in[i]; break;
            default: break;
        }
    }

    const int* ia = (const int*)idx_arr[0];
    const int* ib = (const int*)idx_arr[1];
    float* out = (float*)d_out;

    detect_kernel<<<1, 1>>>(ia, ib);
    outer_kernel<<<BATCH, 128>>>(ia, ib, ftab, rtab);

    dim3 grid2(BATCH / 128, FW / 64, KSPLIT);
    gemm2_kernel<<<grid2, 128>>>(W);

    reduce_kernel<<<(BATCH * FW + 255) / 256, 256>>>(bias, out);
}

// round 7
// speedup vs baseline: 1.4239x; 1.3502x over previous
#include <cuda_runtime.h>
#include <cuda_bf16.h>
#include <cstdint>

// Problem constants
#define BATCH 512
#define SEQ 512
#define FD 128
#define RD 64
#define FW 768
#define KFLAT (FD*RD)   // 8192
#define KSPLIT 8
#define KCHUNK (KFLAT/KSPLIT)  // 1024
#define NUM_FILLERS 50257
#define NUM_ROLES 512

typedef unsigned long long u64;

// Scratch (device globals)
__device__ __nv_bfloat16 g_a_hi[(size_t)BATCH * KFLAT];   // 8.4 MB
__device__ __nv_bfloat16 g_a_lo[(size_t)BATCH * KFLAT];
__device__ __nv_bfloat16 g_w_hi[(size_t)FW * KFLAT];      // 12.6 MB
__device__ __nv_bfloat16 g_w_lo[(size_t)FW * KFLAT];
__device__ float g_partial[(size_t)KSPLIT * BATCH * FW];  // 12.6 MB
__device__ int   g_flags[2];

// ---- packed f32x2 helpers -------------------------------------------------
__device__ __forceinline__ u64 ffma2(u64 a, u64 b, u64 c) {
    u64 d;
    asm("fma.rn.f32x2 %0, %1, %2, %3;" : "=l"(d) : "l"(a), "l"(b), "l"(c));
    return d;
}
__device__ __forceinline__ u64 splat2(float x) {
    u64 r; asm("mov.b64 %0, {%1, %1};" : "=l"(r) : "f"(x)); return r;
}
__device__ __forceinline__ void unpack2(u64 v, float& lo, float& hi) {
    asm("mov.b64 {%0, %1}, %2;" : "=f"(lo), "=f"(hi) : "l"(v));
}

__device__ __forceinline__ uint32_t smem_u32(const void* p) {
    uint32_t a;
    asm("{ .reg .u64 t; cvta.to.shared.u64 t, %1; cvt.u32.u64 %0, t; }" : "=r"(a) : "l"(p));
    return a;
}

// ---- warp mma helpers (sm_80+ baseline, works on compute_100) -------------
#define LDSM4(r, addr) \
    asm volatile("ldmatrix.sync.aligned.m8n8.x4.shared.b16 {%0,%1,%2,%3}, [%4];" \
        : "=r"((r)[0]), "=r"((r)[1]), "=r"((r)[2]), "=r"((r)[3]) : "r"(addr))

#define MMA16816(d, a, b0, b1) \
    asm volatile("mma.sync.aligned.m16n8k16.row.col.f32.bf16.bf16.f32 " \
        "{%0,%1,%2,%3}, {%4,%5,%6,%7}, {%8,%9}, {%0,%1,%2,%3};" \
        : "+f"((d)[0]), "+f"((d)[1]), "+f"((d)[2]), "+f"((d)[3]) \
        : "r"((a)[0]), "r"((a)[1]), "r"((a)[2]), "r"((a)[3]), "r"(b0), "r"(b1))

// ---------------------------------------------------------------------------
// Kernel 0: input disambiguation
// ---------------------------------------------------------------------------
__global__ void detect_kernel(const int* __restrict__ a, const int* __restrict__ b)
{
    if (threadIdx.x != 0 || blockIdx.x != 0) return;
    int odd = 0;
#pragma unroll 8
    for (int i = 0; i < 256; i++) odd |= a[2 * i + 1];
    const int is64 = (odd == 0) ? 1 : 0;
    const int s = is64 ? 2 : 1;
    int amax = 0, bmax = 0;
#pragma unroll 8
    for (int i = 0; i < 256; i++) {
        amax = max(amax, a[i * s]);
        bmax = max(bmax, b[i * s]);
    }
    g_flags[0] = (amax < NUM_ROLES && bmax >= NUM_ROLES) ? 1 : 0;
    g_flags[1] = is64;
}

// ---------------------------------------------------------------------------
// Kernel W: split W fp32 -> bf16 hi/lo
// ---------------------------------------------------------------------------
__global__ __launch_bounds__(256) void convert_w(const float* __restrict__ W)
{
    size_t i = (size_t)blockIdx.x * 256 + threadIdx.x;   // float4 index
    if (i >= (size_t)FW * KFLAT / 4) return;
    float4 v = ((const float4*)W)[i];
    __nv_bfloat16 h0 = __float2bfloat16(v.x), h1 = __float2bfloat16(v.y);
    __nv_bfloat16 h2 = __float2bfloat16(v.z), h3 = __float2bfloat16(v.w);
    __nv_bfloat16 l0 = __float2bfloat16(v.x - __bfloat162float(h0));
    __nv_bfloat16 l1 = __float2bfloat16(v.y - __bfloat162float(h1));
    __nv_bfloat16 l2 = __float2bfloat16(v.z - __bfloat162float(h2));
    __nv_bfloat16 l3 = __float2bfloat16(v.w - __bfloat162float(h3));
    __nv_bfloat162 hp[2] = {{h0, h1}, {h2, h3}};
    __nv_bfloat162 lp[2] = {{l0, l1}, {l2, l3}};
    ((uint2*)g_w_hi)[i] = *(uint2*)hp;
    ((uint2*)g_w_lo)[i] = *(uint2*)lp;
}

// ---------------------------------------------------------------------------
// Kernel 1: per-batch outer products (FFMA2), epilogue emits bf16 hi/lo
// ---------------------------------------------------------------------------
__global__ __launch_bounds__(128) void outer_kernel(
    const int* __restrict__ ia, const int* __restrict__ ib,
    const float* __restrict__ ftab, const float* __restrict__ rtab)
{
    __shared__ float fe[32][FD];
    __shared__ float re[32][RD];
    __shared__ int sf[32];
    __shared__ int sr[32];

    const int b   = blockIdx.x;
    const int tid = threadIdx.x;
    const int m0  = (tid >> 3) * 8;
    const int n0  = (tid & 7) * 8;

    const int swap = g_flags[0];
    const int strd = g_flags[1] ? 2 : 1;
    const int* __restrict__ fidx = swap ? ib : ia;
    const int* __restrict__ ridx = swap ? ia : ib;

    u64 acc2[4][8];
#pragma unroll
    for (int i = 0; i < 4; i++)
#pragma unroll
        for (int j = 0; j < 8; j++) acc2[i][j] = 0ull;

    for (int k0 = 0; k0 < SEQ; k0 += 32) {
        if (tid < 32) {
            size_t e = (size_t)b * SEQ + k0 + tid;
            sf[tid] = min(max(fidx[e * strd], 0), NUM_FILLERS - 1);
            sr[tid] = min(max(ridx[e * strd], 0), NUM_ROLES - 1);
        }
        __syncthreads();
        {
            int kk0 = tid >> 5, d4 = tid & 31;
#pragma unroll
            for (int it = 0; it < 8; it++) {
                int kk = kk0 + it * 4;
                ((float4*)fe[kk])[d4] = ((const float4*)(ftab + (size_t)sf[kk] * FD))[d4];
            }
        }
        {
            int kk0 = tid >> 4, d4 = tid & 15;
#pragma unroll
            for (int it = 0; it < 4; it++) {
                int kk = kk0 + it * 8;
                ((float4*)re[kk])[d4] = ((const float4*)(rtab + (size_t)sr[kk] * RD))[d4];
            }
        }
        __syncthreads();

#pragma unroll
        for (int k = 0; k < 32; k++) {
            ulonglong2 p0 = *(const ulonglong2*)&fe[k][m0];
            ulonglong2 p1 = *(const ulonglong2*)&fe[k][m0 + 4];
            u64 a2[4] = {p0.x, p0.y, p1.x, p1.y};
            float c[8];
            *(float4*)&c[0] = *(const float4*)&re[k][n0];
            *(float4*)&c[4] = *(const float4*)&re[k][n0 + 4];
            u64 c2[8];
#pragma unroll
            for (int j = 0; j < 8; j++) c2[j] = splat2(c[j]);
#pragma unroll
            for (int i = 0; i < 4; i++)
#pragma unroll
                for (int j = 0; j < 8; j++)
                    acc2[i][j] = ffma2(a2[i], c2[j], acc2[i][j]);
        }
        __syncthreads();
    }

    // epilogue: unpack, bf16-split, store 8 bf16 (16B) per row per array
#pragma unroll
    for (int i2 = 0; i2 < 4; i2++) {
        float vlo[8], vhi[8];
#pragma unroll
        for (int j = 0; j < 8; j++) unpack2(acc2[i2][j], vlo[j], vhi[j]);
        float* rows[2] = {vlo, vhi};
#pragma unroll
        for (int r = 0; r < 2; r++) {
            size_t off = (size_t)b * KFLAT + (size_t)(m0 + 2 * i2 + r) * RD + n0;
            __nv_bfloat162 hp[4], lp[4];
#pragma unroll
            for (int j = 0; j < 4; j++) {
                float x0 = rows[r][2 * j], x1 = rows[r][2 * j + 1];
                __nv_bfloat16 h0 = __float2bfloat16(x0), h1 = __float2bfloat16(x1);
                hp[j] = __nv_bfloat162{h0, h1};
                lp[j] = __nv_bfloat162{__float2bfloat16(x0 - __bfloat162float(h0)),
                                       __float2bfloat16(x1 - __bfloat162float(h1))};
            }
            *(uint4*)(g_a_hi + off) = *(uint4*)hp;
            *(uint4*)(g_a_lo + off) = *(uint4*)lp;
        }
    }
}

// ---------------------------------------------------------------------------
// Kernel 2: warp-mma split-K GEMM, bf16 3-pass (hh + hl + lh), fp32 accum.
// grid = (4, 12, KSPLIT), 256 threads (8 warps: 4x2), CTA tile 128x64,
// warp tile 32x32, K-tile 32. smem pitch 40 bf16 (80B) -> conflict-free ldsm.
// ---------------------------------------------------------------------------
#define PITCH 40
#define PITCHB 80
__global__ __launch_bounds__(256) void gemm2_mma()
{
    __shared__ __align__(16) __nv_bfloat16 sAh[128 * PITCH];
    __shared__ __align__(16) __nv_bfloat16 sAl[128 * PITCH];
    __shared__ __align__(16) __nv_bfloat16 sBh[64 * PITCH];
    __shared__ __align__(16) __nv_bfloat16 sBl[64 * PITCH];

    const int tid  = threadIdx.x;
    const int lane = tid & 31;
    const int wid  = tid >> 5;
    const int wm   = (wid & 3) * 32;   // warp M offset in CTA tile
    const int wn   = (wid >> 2) * 32;  // warp N offset

    const int mtile = blockIdx.x, ntile = blockIdx.y, ks = blockIdx.z;
    const size_t arow0 = (size_t)(mtile * 128) * KFLAT;
    const size_t brow0 = (size_t)(ntile * 64) * KFLAT;
    const int kbase = ks * KCHUNK;

    const uint32_t sAh_b = smem_u32(sAh), sAl_b = smem_u32(sAl);
    const uint32_t sBh_b = smem_u32(sBh), sBl_b = smem_u32(sBl);

    // ldmatrix per-lane base offsets (k-step and variant added later)
    // A: row = wm + i*16 + (lane&15), colblk = lane>>4
    const uint32_t a_off0 = (uint32_t)(wm + (lane & 15)) * PITCHB + ((lane >> 4) << 4);
    // B: row = wn + j*16 + ((lane>>4)<<3) + (lane&7), colblk = (lane>>3)&1
    const uint32_t b_off0 = (uint32_t)(wn + ((lane >> 4) << 3) + (lane & 7)) * PITCHB
                          + (((lane >> 3) & 1) << 4);

    float acc[8][4];   // [mi*4 + nj][4]
#pragma unroll
    for (int i = 0; i < 8; i++)
#pragma unroll
        for (int j = 0; j < 4; j++) acc[i][j] = 0.f;

    for (int it = 0; it < KCHUNK / 32; it++) {
        const int kg = kbase + it * 32;
        // ---- load tiles (16B chunks; row pitch 80B) ----
        {
            int row = tid >> 2, c = tid & 3;          // A: 512 chunks, 2/thread/variant
            uint32_t so = (uint32_t)row * PITCHB + c * 16;
            size_t go = arow0 + (size_t)row * KFLAT + kg + c * 8;
#pragma unroll
            for (int u = 0; u < 2; u++) {
                *(uint4*)((char*)sAh + so) = *(const uint4*)(g_a_hi + go);
                *(uint4*)((char*)sAl + so) = *(const uint4*)(g_a_lo + go);
                so += 64 * PITCHB;
                go += (size_t)64 * KFLAT;
            }
        }
        {
            int row = tid >> 2, c = tid & 3;          // B: 256 chunks, 1/thread/variant
            if (row < 64) {
                uint32_t so = (uint32_t)row * PITCHB + c * 16;
                size_t go = brow0 + (size_t)row * KFLAT + kg + c * 8;
                *(uint4*)((char*)sBh + so) = *(const uint4*)(g_w_hi + go);
                *(uint4*)((char*)sBl + so) = *(const uint4*)(g_w_lo + go);
            }
        }
        __syncthreads();

        // ---- compute: 2 k16 steps ----
#pragma unroll
        for (int s = 0; s < 2; s++) {
            const uint32_t koff = s * 32;   // 16 bf16 = 32B
            uint32_t ah[2][4], al[2][4];
#pragma unroll
            for (int i = 0; i < 2; i++) {
                uint32_t off = a_off0 + (uint32_t)(i * 16) * PITCHB + koff;
                LDSM4(ah[i], sAh_b + off);
                LDSM4(al[i], sAl_b + off);
            }
            uint32_t bh[2][4], bl[2][4];
#pragma unroll
            for (int j = 0; j < 2; j++) {
                uint32_t off = b_off0 + (uint32_t)(j * 16) * PITCHB + koff;
                LDSM4(bh[j], sBh_b + off);
                LDSM4(bl[j], sBl_b + off);
            }
#pragma unroll
            for (int i = 0; i < 2; i++)
#pragma unroll
                for (int j = 0; j < 2; j++)
#pragma unroll
                    for (int h = 0; h < 2; h++) {
                        float* d = acc[i * 4 + j * 2 + h];
                        MMA16816(d, ah[i], bh[j][h * 2], bh[j][h * 2 + 1]);  // hh
                        MMA16816(d, ah[i], bl[j][h * 2], bl[j][h * 2 + 1]);  // hl
                        MMA16816(d, al[i], bh[j][h * 2], bh[j][h * 2 + 1]);  // lh
                    }
        }
        __syncthreads();
    }

    // ---- epilogue: d0,d1 -> (row, col..col+1); d2,d3 -> (row+8, ...) ----
    const int rbase = mtile * 128 + wm + (lane >> 2);
    const int cbase = ntile * 64 + wn + (lane & 3) * 2;
    float* P = g_partial + (size_t)ks * BATCH * FW;
#pragma unroll
    for (int i = 0; i < 2; i++)
#pragma unroll
        for (int nj = 0; nj < 4; nj++) {
            float* d = acc[i * 4 + nj];
            size_t r0 = (size_t)(rbase + i * 16) * FW + cbase + nj * 8;
            *(float2*)&P[r0]            = make_float2(d[0], d[1]);
            *(float2*)&P[r0 + 8 * FW]   = make_float2(d[2], d[3]);
        }
}

// ---------------------------------------------------------------------------
// Kernel 3: reduce split-K partials + bias -> out[1][B][FW]
// ---------------------------------------------------------------------------
__global__ void reduce_kernel(const float* __restrict__ bias, float* __restrict__ out)
{
    int idx = blockIdx.x * 256 + threadIdx.x;
    if (idx < BATCH * FW) {
        int n = idx % FW;
        float s = bias[n];
#pragma unroll
        for (int ks = 0; ks < KSPLIT; ks++)
            s += g_partial[(size_t)ks * BATCH * FW + idx];
        out[idx] = s;
    }
}

// ---------------------------------------------------------------------------
extern "C" void kernel_launch(void* const* d_in, const int* in_sizes, int n_in,
                              void* d_out, int out_size)
{
    const void* idx_arr[2] = {nullptr, nullptr};
    int n_idx = 0;
    const float* ftab = nullptr;
    const float* rtab = nullptr;
    const float* W    = nullptr;
    const float* bias = nullptr;

    for (int i = 0; i < n_in; i++) {
        switch (in_sizes[i]) {
            case BATCH * SEQ:
                if (n_idx < 2) idx_arr[n_idx++] = d_in[i];
                break;
            case NUM_FILLERS * FD: ftab = (const float*)d_in[i]; break;
            case NUM_ROLES * RD:   rtab = (const float*)d_in[i]; break;
            case FW * KFLAT:       W    = (const float*)d_in[i]; break;
            case FW:               bias = (const float*)d_in[i]; break;
            default: break;
        }
    }

    const int* ia = (const int*)idx_arr[0];
    const int* ib = (const int*)idx_arr[1];
    float* out = (float*)d_out;

    detect_kernel<<<1, 1>>>(ia, ib);
    convert_w<<<(FW * KFLAT / 4 + 255) / 256, 256>>>(W);
    outer_kernel<<<BATCH, 128>>>(ia, ib, ftab, rtab);

    dim3 grid2(BATCH / 128, FW / 64, KSPLIT);
    gemm2_mma<<<grid2, 256>>>();

    reduce_kernel<<<(BATCH * FW + 255) / 256, 256>>>(bias, out);
}

// round 8
// speedup vs baseline: 1.5779x; 1.1081x over previous
#include <cuda_runtime.h>
#include <cuda_bf16.h>
#include <cstdint>

// Problem constants
#define BATCH 512
#define SEQ 512
#define FD 128
#define RD 64
#define FW 768
#define KFLAT (FD*RD)   // 8192
#define KSPLIT 8
#define KCHUNK (KFLAT/KSPLIT)  // 1024
#define NUM_FILLERS 50257
#define NUM_ROLES 512

// Scratch (device globals)
__device__ __nv_bfloat16 g_a_hi[(size_t)BATCH * KFLAT];   // 8.4 MB
__device__ __nv_bfloat16 g_a_lo[(size_t)BATCH * KFLAT];
__device__ __nv_bfloat16 g_w_hi[(size_t)FW * KFLAT];      // 12.6 MB
__device__ __nv_bfloat16 g_w_lo[(size_t)FW * KFLAT];
__device__ float g_partial[(size_t)KSPLIT * BATCH * FW];  // 12.6 MB
__device__ int   g_flags[2];

__device__ __forceinline__ uint32_t smem_u32(const void* p) {
    uint32_t a;
    asm("{ .reg .u64 t; cvta.to.shared.u64 t, %1; cvt.u32.u64 %0, t; }" : "=r"(a) : "l"(p));
    return a;
}

// ---- warp mma helpers (sm_80+ baseline, works on compute_100) -------------
#define LDSM4(r, addr) \
    asm volatile("ldmatrix.sync.aligned.m8n8.x4.shared.b16 {%0,%1,%2,%3}, [%4];" \
        : "=r"((r)[0]), "=r"((r)[1]), "=r"((r)[2]), "=r"((r)[3]) : "r"(addr))

#define LDSM4T(r, addr) \
    asm volatile("ldmatrix.sync.aligned.m8n8.x4.trans.shared.b16 {%0,%1,%2,%3}, [%4];" \
        : "=r"((r)[0]), "=r"((r)[1]), "=r"((r)[2]), "=r"((r)[3]) : "r"(addr))

#define MMA16816(d, a, b0, b1) \
    asm volatile("mma.sync.aligned.m16n8k16.row.col.f32.bf16.bf16.f32 " \
        "{%0,%1,%2,%3}, {%4,%5,%6,%7}, {%8,%9}, {%0,%1,%2,%3};" \
        : "+f"((d)[0]), "+f"((d)[1]), "+f"((d)[2]), "+f"((d)[3]) \
        : "r"((a)[0]), "r"((a)[1]), "r"((a)[2]), "r"((a)[3]), "r"(b0), "r"(b1))

// split float4 -> bf16 hi/lo packed pairs
__device__ __forceinline__ void bf16_split4(float4 v, uint2& h, uint2& l) {
    __nv_bfloat16 h0 = __float2bfloat16(v.x), h1 = __float2bfloat16(v.y);
    __nv_bfloat16 h2 = __float2bfloat16(v.z), h3 = __float2bfloat16(v.w);
    __nv_bfloat162 hp0{h0, h1}, hp1{h2, h3};
    __nv_bfloat162 lp0{__float2bfloat16(v.x - __bfloat162float(h0)),
                       __float2bfloat16(v.y - __bfloat162float(h1))};
    __nv_bfloat162 lp1{__float2bfloat16(v.z - __bfloat162float(h2)),
                       __float2bfloat16(v.w - __bfloat162float(h3))};
    h.x = *(unsigned*)&hp0; h.y = *(unsigned*)&hp1;
    l.x = *(unsigned*)&lp0; l.y = *(unsigned*)&lp1;
}
__device__ __forceinline__ void bf16_split2(float a, float b, unsigned& h, unsigned& l) {
    __nv_bfloat16 h0 = __float2bfloat16(a), h1 = __float2bfloat16(b);
    __nv_bfloat162 hp{h0, h1};
    __nv_bfloat162 lp{__float2bfloat16(a - __bfloat162float(h0)),
                      __float2bfloat16(b - __bfloat162float(h1))};
    h = *(unsigned*)&hp; l = *(unsigned*)&lp;
}

// ---------------------------------------------------------------------------
// Kernel 0: input disambiguation
// ---------------------------------------------------------------------------
__global__ void detect_kernel(const int* __restrict__ a, const int* __restrict__ b)
{
    if (threadIdx.x != 0 || blockIdx.x != 0) return;
    int odd = 0;
#pragma unroll 8
    for (int i = 0; i < 256; i++) odd |= a[2 * i + 1];
    const int is64 = (odd == 0) ? 1 : 0;
    const int s = is64 ? 2 : 1;
    int amax = 0, bmax = 0;
#pragma unroll 8
    for (int i = 0; i < 256; i++) {
        amax = max(amax, a[i * s]);
        bmax = max(bmax, b[i * s]);
    }
    g_flags[0] = (amax < NUM_ROLES && bmax >= NUM_ROLES) ? 1 : 0;
    g_flags[1] = is64;
}

// ---------------------------------------------------------------------------
// Kernel W: split W fp32 -> bf16 hi/lo
// ---------------------------------------------------------------------------
__global__ __launch_bounds__(256) void convert_w(const float* __restrict__ W)
{
    size_t i = (size_t)blockIdx.x * 256 + threadIdx.x;
    if (i >= (size_t)FW * KFLAT / 4) return;
    float4 v = ((const float4*)W)[i];
    uint2 h, l;
    bf16_split4(v, h, l);
    ((uint2*)g_w_hi)[i] = h;
    ((uint2*)g_w_lo)[i] = l;
}

// ---------------------------------------------------------------------------
// Kernel 1: tensorized outer products.
//   outer[b] = fe^T @ re : M=128(FD) x N=64(RD) x K=512(seq), bf16 3-pass.
// grid = 512 (CTA per batch), 256 threads (8 warps 4x2), warp tile 32x32.
// fe/re gathered fp32 -> bf16 hi/lo smem [s][dim]; A,B frags via ldmatrix.trans.
// ---------------------------------------------------------------------------
#define FE_PITCH 136   // bf16 elems per row: 272B (mod 128 = 16 -> conflict-free)
#define RE_PITCH 72    // 144B
__global__ __launch_bounds__(256) void outer_tc(
    const int* __restrict__ ia, const int* __restrict__ ib,
    const float* __restrict__ ftab, const float* __restrict__ rtab)
{
    __shared__ __align__(16) __nv_bfloat16 feh[32 * FE_PITCH];
    __shared__ __align__(16) __nv_bfloat16 fel[32 * FE_PITCH];
    __shared__ __align__(16) __nv_bfloat16 reh[32 * RE_PITCH];
    __shared__ __align__(16) __nv_bfloat16 rel[32 * RE_PITCH];
    __shared__ int sf[32], sr[32];

    const int b    = blockIdx.x;
    const int tid  = threadIdx.x;
    const int lane = tid & 31;
    const int wid  = tid >> 5;
    const int wm   = (wid & 3) * 32;   // M offset (FD)
    const int wn   = (wid >> 2) * 32;  // N offset (RD)

    const int swap = g_flags[0];
    const int strd = g_flags[1] ? 2 : 1;
    const int* __restrict__ fidx = swap ? ib : ia;
    const int* __restrict__ ridx = swap ? ia : ib;

    const uint32_t feh_b = smem_u32(feh), fel_b = smem_u32(fel);
    const uint32_t reh_b = smem_u32(reh), rel_b = smem_u32(rel);

    // trans-ldmatrix lane byte offsets (k-step / mi / n16 added later):
    // A: matrices (k0,m0),(k0,m8),(k8,m0),(k8,m8); rows = seq dim
    const uint32_t aoff = (uint32_t)((lane & 7) + ((lane >> 4) & 1) * 8) * (FE_PITCH * 2)
                        + (uint32_t)(wm + ((lane >> 3) & 1) * 8) * 2;
    // B: matrices (k0,n0),(k8,n0),(k0,n8),(k8,n8)
    const uint32_t boff = (uint32_t)((lane & 7) + ((lane >> 3) & 1) * 8) * (RE_PITCH * 2)
                        + (uint32_t)(wn + ((lane >> 4) & 1) * 8) * 2;

    float acc[2][4][4];   // [mi][nj = n16*2+h][4]
#pragma unroll
    for (int i = 0; i < 2; i++)
#pragma unroll
        for (int j = 0; j < 4; j++)
#pragma unroll
            for (int q = 0; q < 4; q++) acc[i][j][q] = 0.f;

    for (int k0 = 0; k0 < SEQ; k0 += 32) {
        if (tid < 32) {
            size_t e = (size_t)b * SEQ + k0 + tid;
            sf[tid] = min(max(fidx[e * strd], 0), NUM_FILLERS - 1);
            sr[tid] = min(max(ridx[e * strd], 0), NUM_ROLES - 1);
        }
        __syncthreads();

        // gather fe: 32 s-rows x 32 float4 = 1024 chunks / 256 thr = 4 each
#pragma unroll
        for (int it = 0; it < 4; it++) {
            int id = it * 256 + tid;
            int row = id >> 5, c4 = id & 31;
            float4 v = ((const float4*)(ftab + (size_t)sf[row] * FD))[c4];
            uint2 h, l;
            bf16_split4(v, h, l);
            int off = row * FE_PITCH + c4 * 4;
            *(uint2*)(feh + off) = h;
            *(uint2*)(fel + off) = l;
        }
        // gather re: 32 x 16 float4 = 512 chunks / 256 thr = 2 each
#pragma unroll
        for (int it = 0; it < 2; it++) {
            int id = it * 256 + tid;
            int row = id >> 4, c4 = id & 15;
            float4 v = ((const float4*)(rtab + (size_t)sr[row] * RD))[c4];
            uint2 h, l;
            bf16_split4(v, h, l);
            int off = row * RE_PITCH + c4 * 4;
            *(uint2*)(reh + off) = h;
            *(uint2*)(rel + off) = l;
        }
        __syncthreads();

#pragma unroll
        for (int s = 0; s < 2; s++) {
            const uint32_t arow = aoff + (uint32_t)(s * 16) * (FE_PITCH * 2);
            const uint32_t brow = boff + (uint32_t)(s * 16) * (RE_PITCH * 2);
            uint32_t ah[2][4], al[2][4];
#pragma unroll
            for (int mi = 0; mi < 2; mi++) {
                LDSM4T(ah[mi], feh_b + arow + mi * 32);
                LDSM4T(al[mi], fel_b + arow + mi * 32);
            }
            uint32_t bh[2][4], bl[2][4];
#pragma unroll
            for (int n16 = 0; n16 < 2; n16++) {
                LDSM4T(bh[n16], reh_b + brow + n16 * 32);
                LDSM4T(bl[n16], rel_b + brow + n16 * 32);
            }
#pragma unroll
            for (int mi = 0; mi < 2; mi++)
#pragma unroll
                for (int n16 = 0; n16 < 2; n16++)
#pragma unroll
                    for (int h = 0; h < 2; h++) {
                        float* d = acc[mi][n16 * 2 + h];
                        MMA16816(d, ah[mi], bh[n16][h * 2], bh[n16][h * 2 + 1]);  // hh
                        MMA16816(d, ah[mi], bl[n16][h * 2], bl[n16][h * 2 + 1]);  // hl
                        MMA16816(d, al[mi], bh[n16][h * 2], bh[n16][h * 2 + 1]);  // lh
                    }
        }
        __syncthreads();
    }

    // epilogue: frag (row = lane>>2 [+8], col pair = (lane&3)*2) -> bf16 hi/lo
    const int rrow = lane >> 2, rcol = (lane & 3) * 2;
#pragma unroll
    for (int mi = 0; mi < 2; mi++)
#pragma unroll
        for (int nj = 0; nj < 4; nj++) {
            float* d = acc[mi][nj];
            int m = wm + mi * 16 + rrow;
            int n = wn + nj * 8 + rcol;
            size_t off = (size_t)b * KFLAT + (size_t)m * RD + n;
            unsigned h, l;
            bf16_split2(d[0], d[1], h, l);
            *(unsigned*)(g_a_hi + off) = h;
            *(unsigned*)(g_a_lo + off) = l;
            bf16_split2(d[2], d[3], h, l);
            *(unsigned*)(g_a_hi + off + 8 * RD) = h;
            *(unsigned*)(g_a_lo + off + 8 * RD) = l;
        }
}

// ---------------------------------------------------------------------------
// Kernel 2: warp-mma split-K GEMM, bf16 3-pass (hh + hl + lh), fp32 accum.
// grid = (4, 12, KSPLIT), 256 threads (8 warps: 4x2), CTA tile 128x64,
// warp tile 32x32, K-tile 32. smem pitch 40 bf16 (80B) -> conflict-free ldsm.
// ---------------------------------------------------------------------------
#define PITCH 40
#define PITCHB 80
__global__ __launch_bounds__(256) void gemm2_mma()
{
    __shared__ __align__(16) __nv_bfloat16 sAh[128 * PITCH];
    __shared__ __align__(16) __nv_bfloat16 sAl[128 * PITCH];
    __shared__ __align__(16) __nv_bfloat16 sBh[64 * PITCH];
    __shared__ __align__(16) __nv_bfloat16 sBl[64 * PITCH];

    const int tid  = threadIdx.x;
    const int lane = tid & 31;
    const int wid  = tid >> 5;
    const int wm   = (wid & 3) * 32;
    const int wn   = (wid >> 2) * 32;

    const int mtile = blockIdx.x, ntile = blockIdx.y, ks = blockIdx.z;
    const size_t arow0 = (size_t)(mtile * 128) * KFLAT;
    const size_t brow0 = (size_t)(ntile * 64) * KFLAT;
    const int kbase = ks * KCHUNK;

    const uint32_t sAh_b = smem_u32(sAh), sAl_b = smem_u32(sAl);
    const uint32_t sBh_b = smem_u32(sBh), sBl_b = smem_u32(sBl);

    const uint32_t a_off0 = (uint32_t)(wm + (lane & 15)) * PITCHB + ((lane >> 4) << 4);
    const uint32_t b_off0 = (uint32_t)(wn + ((lane >> 4) << 3) + (lane & 7)) * PITCHB
                          + (((lane >> 3) & 1) << 4);

    float acc[8][4];
#pragma unroll
    for (int i = 0; i < 8; i++)
#pragma unroll
        for (int j = 0; j < 4; j++) acc[i][j] = 0.f;

    for (int it = 0; it < KCHUNK / 32; it++) {
        const int kg = kbase + it * 32;
        {
            int row = tid >> 2, c = tid & 3;
            uint32_t so = (uint32_t)row * PITCHB + c * 16;
            size_t go = arow0 + (size_t)row * KFLAT + kg + c * 8;
#pragma unroll
            for (int u = 0; u < 2; u++) {
                *(uint4*)((char*)sAh + so) = *(const uint4*)(g_a_hi + go);
                *(uint4*)((char*)sAl + so) = *(const uint4*)(g_a_lo + go);
                so += 64 * PITCHB;
                go += (size_t)64 * KFLAT;
            }
        }
        {
            int row = tid >> 2, c = tid & 3;
            if (row < 64) {
                uint32_t so = (uint32_t)row * PITCHB + c * 16;
                size_t go = brow0 + (size_t)row * KFLAT + kg + c * 8;
                *(uint4*)((char*)sBh + so) = *(const uint4*)(g_w_hi + go);
                *(uint4*)((char*)sBl + so) = *(const uint4*)(g_w_lo + go);
            }
        }
        __syncthreads();

#pragma unroll
        for (int s = 0; s < 2; s++) {
            const uint32_t koff = s * 32;
            uint32_t ah[2][4], al[2][4];
#pragma unroll
            for (int i = 0; i < 2; i++) {
                uint32_t off = a_off0 + (uint32_t)(i * 16) * PITCHB + koff;
                LDSM4(ah[i], sAh_b + off);
                LDSM4(al[i], sAl_b + off);
            }
            uint32_t bh[2][4], bl[2][4];
#pragma unroll
            for (int j = 0; j < 2; j++) {
                uint32_t off = b_off0 + (uint32_t)(j * 16) * PITCHB + koff;
                LDSM4(bh[j], sBh_b + off);
                LDSM4(bl[j], sBl_b + off);
            }
#pragma unroll
            for (int i = 0; i < 2; i++)
#pragma unroll
                for (int j = 0; j < 2; j++)
#pragma unroll
                    for (int h = 0; h < 2; h++) {
                        float* d = acc[i * 4 + j * 2 + h];
                        MMA16816(d, ah[i], bh[j][h * 2], bh[j][h * 2 + 1]);
                        MMA16816(d, ah[i], bl[j][h * 2], bl[j][h * 2 + 1]);
                        MMA16816(d, al[i], bh[j][h * 2], bh[j][h * 2 + 1]);
                    }
        }
        __syncthreads();
    }

    const int rbase = mtile * 128 + wm + (lane >> 2);
    const int cbase = ntile * 64 + wn + (lane & 3) * 2;
    float* P = g_partial + (size_t)ks * BATCH * FW;
#pragma unroll
    for (int i = 0; i < 2; i++)
#pragma unroll
        for (int nj = 0; nj < 4; nj++) {
            float* d = acc[i * 4 + nj];
            size_t r0 = (size_t)(rbase + i * 16) * FW + cbase + nj * 8;
            *(float2*)&P[r0]          = make_float2(d[0], d[1]);
            *(float2*)&P[r0 + 8 * FW] = make_float2(d[2], d[3]);
        }
}

// ---------------------------------------------------------------------------
// Kernel 3: reduce split-K partials + bias -> out[1][B][FW]
// ---------------------------------------------------------------------------
__global__ void reduce_kernel(const float* __restrict__ bias, float* __restrict__ out)
{
    int idx = blockIdx.x * 256 + threadIdx.x;
    if (idx < BATCH * FW) {
        int n = idx % FW;
        float s = bias[n];
#pragma unroll
        for (int ks = 0; ks < KSPLIT; ks++)
            s += g_partial[(size_t)ks * BATCH * FW + idx];
        out[idx] = s;
    }
}

// ---------------------------------------------------------------------------
extern "C" void kernel_launch(void* const* d_in, const int* in_sizes, int n_in,
                              void* d_out, int out_size)
{
    const void* idx_arr[2] = {nullptr, nullptr};
    int n_idx = 0;
    const float* ftab = nullptr;
    const float* rtab = nullptr;
    const float* W    = nullptr;
    const float* bias = nullptr;

    for (int i = 0; i < n_in; i++) {
        switch (in_sizes[i]) {
            case BATCH * SEQ:
                if (n_idx < 2) idx_arr[n_idx++] = d_in[i];
                break;
            case NUM_FILLERS * FD: ftab = (const float*)d_in[i]; break;
            case NUM_ROLES * RD:   rtab = (const float*)d_in[i]; break;
            case FW * KFLAT:       W    = (const float*)d_in[i]; break;
            case FW:               bias = (const float*)d_in[i]; break;
            default: break;
        }
    }

    const int* ia = (const int*)idx_arr[0];
    const int* ib = (const int*)idx_arr[1];
    float* out = (float*)d_out;

    detect_kernel<<<1, 1>>>(ia, ib);
    convert_w<<<(FW * KFLAT / 4 + 255) / 256, 256>>>(W);
    outer_tc<<<BATCH, 256>>>(ia, ib, ftab, rtab);

    dim3 grid2(BATCH / 128, FW / 64, KSPLIT);
    gemm2_mma<<<grid2, 256>>>();

    reduce_kernel<<<(BATCH * FW + 255) / 256, 256>>>(bias, out);
}

// round 10
// speedup vs baseline: 1.9882x; 1.2600x over previous
#include <cuda_runtime.h>
#include <cuda_bf16.h>
#include <cstdint>

// Problem constants
#define BATCH 512
#define SEQ 512
#define FD 128
#define RD 64
#define FW 768
#define KFLAT (FD*RD)   // 8192
#define KSPLIT 8
#define KCHUNK (KFLAT/KSPLIT)  // 1024
#define NUM_FILLERS 50257
#define NUM_ROLES 512

// Scratch (device globals)
__device__ __nv_bfloat16 g_f_hi[(size_t)NUM_FILLERS * FD]; // 12.9 MB
__device__ __nv_bfloat16 g_f_lo[(size_t)NUM_FILLERS * FD];
__device__ __nv_bfloat16 g_r_hi[(size_t)NUM_ROLES * RD];   // 64 KB
__device__ __nv_bfloat16 g_r_lo[(size_t)NUM_ROLES * RD];
__device__ __nv_bfloat16 g_a_hi[(size_t)BATCH * KFLAT];    // 8.4 MB
__device__ __nv_bfloat16 g_a_lo[(size_t)BATCH * KFLAT];
__device__ __nv_bfloat16 g_w_hi[(size_t)FW * KFLAT];       // 12.6 MB
__device__ __nv_bfloat16 g_w_lo[(size_t)FW * KFLAT];
__device__ float g_partial[(size_t)KSPLIT * BATCH * FW];   // 12.6 MB
__device__ int   g_flags[2];

__device__ __forceinline__ uint32_t smem_u32(const void* p) {
    uint32_t a;
    asm("{ .reg .u64 t; cvta.to.shared.u64 t, %1; cvt.u32.u64 %0, t; }" : "=r"(a) : "l"(p));
    return a;
}

// ---- cp.async helpers -----------------------------------------------------
#define CP_ASYNC16(dst, src) \
    asm volatile("cp.async.cg.shared.global [%0], [%1], 16;" :: "r"(dst), "l"(src))
#define CP_COMMIT() asm volatile("cp.async.commit_group;" ::: "memory")
#define CP_WAIT(N)  asm volatile("cp.async.wait_group %0;" :: "n"(N) : "memory")

// ---- warp mma helpers -----------------------------------------------------
#define LDSM4(r, addr) \
    asm volatile("ldmatrix.sync.aligned.m8n8.x4.shared.b16 {%0,%1,%2,%3}, [%4];" \
        : "=r"((r)[0]), "=r"((r)[1]), "=r"((r)[2]), "=r"((r)[3]) : "r"(addr))

#define LDSM4T(r, addr) \
    asm volatile("ldmatrix.sync.aligned.m8n8.x4.trans.shared.b16 {%0,%1,%2,%3}, [%4];" \
        : "=r"((r)[0]), "=r"((r)[1]), "=r"((r)[2]), "=r"((r)[3]) : "r"(addr))

#define MMA16816(d, a, b0, b1) \
    asm volatile("mma.sync.aligned.m16n8k16.row.col.f32.bf16.bf16.f32 " \
        "{%0,%1,%2,%3}, {%4,%5,%6,%7}, {%8,%9}, {%0,%1,%2,%3};" \
        : "+f"((d)[0]), "+f"((d)[1]), "+f"((d)[2]), "+f"((d)[3]) \
        : "r"((a)[0]), "r"((a)[1]), "r"((a)[2]), "r"((a)[3]), "r"(b0), "r"(b1))

__device__ __forceinline__ void bf16_split4(float4 v, uint2& h, uint2& l) {
    __nv_bfloat16 h0 = __float2bfloat16(v.x), h1 = __float2bfloat16(v.y);
    __nv_bfloat16 h2 = __float2bfloat16(v.z), h3 = __float2bfloat16(v.w);
    __nv_bfloat162 hp0{h0, h1}, hp1{h2, h3};
    __nv_bfloat162 lp0{__float2bfloat16(v.x - __bfloat162float(h0)),
                       __float2bfloat16(v.y - __bfloat162float(h1))};
    __nv_bfloat162 lp1{__float2bfloat16(v.z - __bfloat162float(h2)),
                       __float2bfloat16(v.w - __bfloat162float(h3))};
    h.x = *(unsigned*)&hp0; h.y = *(unsigned*)&hp1;
    l.x = *(unsigned*)&lp0; l.y = *(unsigned*)&lp1;
}
__device__ __forceinline__ void bf16_split2(float a, float b, unsigned& h, unsigned& l) {
    __nv_bfloat16 h0 = __float2bfloat16(a), h1 = __float2bfloat16(b);
    __nv_bfloat162 hp{h0, h1};
    __nv_bfloat162 lp{__float2bfloat16(a - __bfloat162float(h0)),
                      __float2bfloat16(b - __bfloat162float(h1))};
    h = *(unsigned*)&hp; l = *(unsigned*)&lp;
}

// ---------------------------------------------------------------------------
// Kernel 0: input disambiguation
// ---------------------------------------------------------------------------
__global__ void detect_kernel(const int* __restrict__ a, const int* __restrict__ b)
{
    if (threadIdx.x != 0 || blockIdx.x != 0) return;
    int odd = 0;
#pragma unroll 8
    for (int i = 0; i < 256; i++) odd |= a[2 * i + 1];
    const int is64 = (odd == 0) ? 1 : 0;
    const int s = is64 ? 2 : 1;
    int amax = 0, bmax = 0;
#pragma unroll 8
    for (int i = 0; i < 256; i++) {
        amax = max(amax, a[i * s]);
        bmax = max(bmax, b[i * s]);
    }
    g_flags[0] = (amax < NUM_ROLES && bmax >= NUM_ROLES) ? 1 : 0;
    g_flags[1] = is64;
}

// ---------------------------------------------------------------------------
// One-shot fp32 -> bf16 hi/lo converters
// ---------------------------------------------------------------------------
__global__ __launch_bounds__(256) void convert_w(const float* __restrict__ W)
{
    size_t i = (size_t)blockIdx.x * 256 + threadIdx.x;
    if (i >= (size_t)FW * KFLAT / 4) return;
    float4 v = ((const float4*)W)[i];
    uint2 h, l;
    bf16_split4(v, h, l);
    ((uint2*)g_w_hi)[i] = h;
    ((uint2*)g_w_lo)[i] = l;
}
__global__ __launch_bounds__(256) void convert_ftab(const float* __restrict__ T)
{
    size_t i = (size_t)blockIdx.x * 256 + threadIdx.x;
    if (i >= (size_t)NUM_FILLERS * FD / 4) return;
    float4 v = ((const float4*)T)[i];
    uint2 h, l;
    bf16_split4(v, h, l);
    ((uint2*)g_f_hi)[i] = h;
    ((uint2*)g_f_lo)[i] = l;
}
__global__ __launch_bounds__(256) void convert_rtab(const float* __restrict__ T)
{
    size_t i = (size_t)blockIdx.x * 256 + threadIdx.x;
    if (i >= (size_t)NUM_ROLES * RD / 4) return;
    float4 v = ((const float4*)T)[i];
    uint2 h, l;
    bf16_split4(v, h, l);
    ((uint2*)g_r_hi)[i] = h;
    ((uint2*)g_r_lo)[i] = l;
}

// ---------------------------------------------------------------------------
// Kernel 1: tensorized outer products, cp.async double-buffered gathers.
//   outer[b] = fe^T @ re : M=128 x N=64 x K=512, bf16 3-pass, fp32 accum.
// grid = 512, 256 threads (8 warps 4x2), warp tile 32x32.
// Dynamic smem: 2 stages x (feh 8704 + fel 8704 + reh 4608 + rel 4608).
// ---------------------------------------------------------------------------
#define FE_PITCHB 272
#define RE_PITCHB 144
#define O_FEH 0
#define O_FEL 8704
#define O_REH 17408
#define O_REL 22016
#define O_STAGE 26624
#define OUTER_DYN (2 * O_STAGE)
#define O_NT (SEQ / 32)   // 16

__global__ __launch_bounds__(256) void outer_tc(
    const int* __restrict__ ia, const int* __restrict__ ib)
{
    extern __shared__ char dsm[];
    __shared__ int sf[SEQ], sr[SEQ];

    const int b    = blockIdx.x;
    const int tid  = threadIdx.x;
    const int lane = tid & 31;
    const int wid  = tid >> 5;
    const int wm   = (wid & 3) * 32;
    const int wn   = (wid >> 2) * 32;

    const int swap = g_flags[0];
    const int strd = g_flags[1] ? 2 : 1;
    const int* __restrict__ fidx = swap ? ib : ia;
    const int* __restrict__ ridx = swap ? ia : ib;

    // preload + clamp all 512 indices
#pragma unroll
    for (int i = tid; i < SEQ; i += 256) {
        size_t e = (size_t)b * SEQ + i;
        sf[i] = min(max(fidx[e * strd], 0), NUM_FILLERS - 1);
        sr[i] = min(max(ridx[e * strd], 0), NUM_ROLES - 1);
    }
    __syncthreads();

    const uint32_t smb = smem_u32(dsm);

    // per-thread gather mapping
    const int fr = tid >> 4, fc = tid & 15;   // fe: rows fr, fr+16 (2 chunks/variant)
    const int rr = tid >> 3, rc = tid & 7;    // re: 1 chunk/variant

    auto issue_tile = [&](int kt, int st) {
        const int k0 = kt * 32;
        const uint32_t base = smb + st * O_STAGE;
#pragma unroll
        for (int u = 0; u < 2; u++) {
            int row = fr + u * 16;
            uint32_t d = base + row * FE_PITCHB + fc * 16;
            size_t s = (size_t)sf[k0 + row] * FD + fc * 8;
            CP_ASYNC16(d + O_FEH, g_f_hi + s);
            CP_ASYNC16(d + O_FEL, g_f_lo + s);
        }
        {
            uint32_t d = base + rr * RE_PITCHB + rc * 16;
            size_t s = (size_t)sr[k0 + rr] * RD + rc * 8;
            CP_ASYNC16(d + O_REH, g_r_hi + s);
            CP_ASYNC16(d + O_REL, g_r_lo + s);
        }
        CP_COMMIT();
    };

    // ldmatrix.trans lane offsets
    const uint32_t aoff = (uint32_t)((lane & 7) + ((lane >> 4) & 1) * 8) * FE_PITCHB
                        + (uint32_t)(wm + ((lane >> 3) & 1) * 8) * 2;
    const uint32_t boff = (uint32_t)((lane & 7) + ((lane >> 3) & 1) * 8) * RE_PITCHB
                        + (uint32_t)(wn + ((lane >> 4) & 1) * 8) * 2;

    float acc[2][4][4];
#pragma unroll
    for (int i = 0; i < 2; i++)
#pragma unroll
        for (int j = 0; j < 4; j++)
#pragma unroll
            for (int q = 0; q < 4; q++) acc[i][j][q] = 0.f;

    issue_tile(0, 0);

    for (int kt = 0; kt < O_NT; kt++) {
        const int st = kt & 1;
        if (kt + 1 < O_NT) { issue_tile(kt + 1, st ^ 1); CP_WAIT(1); }
        else               { CP_WAIT(0); }
        __syncthreads();

        const uint32_t base = smb + st * O_STAGE;
#pragma unroll
        for (int s = 0; s < 2; s++) {
            const uint32_t arow = base + O_FEH + aoff + (uint32_t)(s * 16) * FE_PITCHB;
            const uint32_t alrow = arow + (O_FEL - O_FEH);
            const uint32_t brow = base + O_REH + boff + (uint32_t)(s * 16) * RE_PITCHB;
            const uint32_t blrow = brow + (O_REL - O_REH);
            uint32_t ah[2][4], al[2][4];
#pragma unroll
            for (int mi = 0; mi < 2; mi++) {
                LDSM4T(ah[mi], arow + mi * 32);
                LDSM4T(al[mi], alrow + mi * 32);
            }
            uint32_t bh[2][4], bl[2][4];
#pragma unroll
            for (int n16 = 0; n16 < 2; n16++) {
                LDSM4T(bh[n16], brow + n16 * 32);
                LDSM4T(bl[n16], blrow + n16 * 32);
            }
#pragma unroll
            for (int mi = 0; mi < 2; mi++)
#pragma unroll
                for (int n16 = 0; n16 < 2; n16++)
#pragma unroll
                    for (int h = 0; h < 2; h++) {
                        float* d = acc[mi][n16 * 2 + h];
                        MMA16816(d, ah[mi], bh[n16][h * 2], bh[n16][h * 2 + 1]);
                        MMA16816(d, ah[mi], bl[n16][h * 2], bl[n16][h * 2 + 1]);
                        MMA16816(d, al[mi], bh[n16][h * 2], bh[n16][h * 2 + 1]);
                    }
        }
        __syncthreads();
    }

    const int rrow = lane >> 2, rcol = (lane & 3) * 2;
#pragma unroll
    for (int mi = 0; mi < 2; mi++)
#pragma unroll
        for (int nj = 0; nj < 4; nj++) {
            float* d = acc[mi][nj];
            int m = wm + mi * 16 + rrow;
            int n = wn + nj * 8 + rcol;
            size_t off = (size_t)b * KFLAT + (size_t)m * RD + n;
            unsigned h, l;
            bf16_split2(d[0], d[1], h, l);
            *(unsigned*)(g_a_hi + off) = h;
            *(unsigned*)(g_a_lo + off) = l;
            bf16_split2(d[2], d[3], h, l);
            *(unsigned*)(g_a_hi + off + 8 * RD) = h;
            *(unsigned*)(g_a_lo + off + 8 * RD) = l;
        }
}

// ---------------------------------------------------------------------------
// Kernel 2: warp-mma split-K GEMM, cp.async double-buffered.
// grid = (4, 12, KSPLIT), 256 threads, CTA 128x64, warp 32x32, K-tile 32.
// Dynamic smem: 2 stages x (Ah 10240 + Al 10240 + Bh 5120 + Bl 5120).
// ---------------------------------------------------------------------------
#define PITCHB 80
#define G_AH 0
#define G_AL 10240
#define G_BH 20480
#define G_BL 25600
#define G_STAGE 30720
#define GEMM2_DYN (2 * G_STAGE)
#define G_NT (KCHUNK / 32)   // 32

__global__ __launch_bounds__(256) void gemm2_mma()
{
    extern __shared__ char dsm[];
    const int tid  = threadIdx.x;
    const int lane = tid & 31;
    const int wid  = tid >> 5;
    const int wm   = (wid & 3) * 32;
    const int wn   = (wid >> 2) * 32;

    const int mtile = blockIdx.x, ntile = blockIdx.y, ks = blockIdx.z;
    const size_t arow0 = (size_t)(mtile * 128) * KFLAT;
    const size_t brow0 = (size_t)(ntile * 64) * KFLAT;
    const int kbase = ks * KCHUNK;

    const uint32_t smb = smem_u32(dsm);
    const int row = tid >> 2, c = tid & 3;

    auto issue_tile = [&](int it, int st) {
        const int kg = kbase + it * 32;
        const uint32_t base = smb + st * G_STAGE;
#pragma unroll
        for (int u = 0; u < 2; u++) {
            int r2 = row + u * 64;
            uint32_t d = base + r2 * PITCHB + c * 16;
            size_t s = arow0 + (size_t)r2 * KFLAT + kg + c * 8;
            CP_ASYNC16(d + G_AH, g_a_hi + s);
            CP_ASYNC16(d + G_AL, g_a_lo + s);
        }
        {
            uint32_t d = base + row * PITCHB + c * 16;
            size_t s = brow0 + (size_t)row * KFLAT + kg + c * 8;
            CP_ASYNC16(d + G_BH, g_w_hi + s);
            CP_ASYNC16(d + G_BL, g_w_lo + s);
        }
        CP_COMMIT();
    };

    const uint32_t a_off0 = (uint32_t)(wm + (lane & 15)) * PITCHB + ((lane >> 4) << 4);
    const uint32_t b_off0 = (uint32_t)(wn + ((lane >> 4) << 3) + (lane & 7)) * PITCHB
                          + (((lane >> 3) & 1) << 4);

    float acc[8][4];
#pragma unroll
    for (int i = 0; i < 8; i++)
#pragma unroll
        for (int j = 0; j < 4; j++) acc[i][j] = 0.f;

    issue_tile(0, 0);

    for (int it = 0; it < G_NT; it++) {
        const int st = it & 1;
        if (it + 1 < G_NT) { issue_tile(it + 1, st ^ 1); CP_WAIT(1); }
        else               { CP_WAIT(0); }
        __syncthreads();

        const uint32_t base = smb + st * G_STAGE;
#pragma unroll
        for (int s = 0; s < 2; s++) {
            const uint32_t koff = s * 32;
            uint32_t ah[2][4], al[2][4];
#pragma unroll
            for (int i = 0; i < 2; i++) {
                uint32_t off = a_off0 + (uint32_t)(i * 16) * PITCHB + koff;
                LDSM4(ah[i], base + G_AH + off);
                LDSM4(al[i], base + G_AL + off);
            }
            uint32_t bh[2][4], bl[2][4];
#pragma unroll
            for (int j = 0; j < 2; j++) {
                uint32_t off = b_off0 + (uint32_t)(j * 16) * PITCHB + koff;
                LDSM4(bh[j], base + G_BH + off);
                LDSM4(bl[j], base + G_BL + off);
            }
#pragma unroll
            for (int i = 0; i < 2; i++)
#pragma unroll
                for (int j = 0; j < 2; j++)
#pragma unroll
                    for (int h = 0; h < 2; h++) {
                        float* d = acc[i * 4 + j * 2 + h];
                        MMA16816(d, ah[i], bh[j][h * 2], bh[j][h * 2 + 1]);
                        MMA16816(d, ah[i], bl[j][h * 2], bl[j][h * 2 + 1]);
                        MMA16816(d, al[i], bh[j][h * 2], bh[j][h * 2 + 1]);
                    }
        }
        __syncthreads();
    }

    const int rbase = mtile * 128 + wm + (lane >> 2);
    const int cbase = ntile * 64 + wn + (lane & 3) * 2;
    float* P = g_partial + (size_t)ks * BATCH * FW;
#pragma unroll
    for (int i = 0; i < 2; i++)
#pragma unroll
        for (int nj = 0; nj < 4; nj++) {
            float* d = acc[i * 4 + nj];
            size_t r0 = (size_t)(rbase + i * 16) * FW + cbase + nj * 8;
            *(float2*)&P[r0]          = make_float2(d[0], d[1]);
            *(float2*)&P[r0 + 8 * FW] = make_float2(d[2], d[3]);
        }
}

// ---------------------------------------------------------------------------
// Kernel 3: reduce split-K partials + bias -> out[1][B][FW]
// ---------------------------------------------------------------------------
__global__ void reduce_kernel(const float* __restrict__ bias, float* __restrict__ out)
{
    int idx = blockIdx.x * 256 + threadIdx.x;
    if (idx < BATCH * FW) {
        int n = idx % FW;
        float s = bias[n];
#pragma unroll
        for (int ks = 0; ks < KSPLIT; ks++)
            s += g_partial[(size_t)ks * BATCH * FW + idx];
        out[idx] = s;
    }
}

// ---------------------------------------------------------------------------
extern "C" void kernel_launch(void* const* d_in, const int* in_sizes, int n_in,
                              void* d_out, int out_size)
{
    const void* idx_arr[2] = {nullptr, nullptr};
    int n_idx = 0;
    const float* ftab = nullptr;
    const float* rtab = nullptr;
    const float* W    = nullptr;
    const float* bias = nullptr;

    for (int i = 0; i < n_in; i++) {
        switch (in_sizes[i]) {
            case BATCH * SEQ:
                if (n_idx < 2) idx_arr[n_idx++] = d_in[i];
                break;
            case NUM_FILLERS * FD: ftab = (const float*)d_in[i]; break;
            case NUM_ROLES * RD:   rtab = (const float*)d_in[i]; break;
            case FW * KFLAT:       W    = (const float*)d_in[i]; break;
            case FW:               bias = (const float*)d_in[i]; break;
            default: break;
        }
    }

    const int* ia = (const int*)idx_arr[0];
    const int* ib = (const int*)idx_arr[1];
    float* out = (float*)d_out;

    // Set smem attributes once, on the first (uncaptured) correctness call.
    static bool attr_done = false;
    if (!attr_done) {
        cudaFuncSetAttribute(outer_tc, cudaFuncAttributeMaxDynamicSharedMemorySize, OUTER_DYN);
        cudaFuncSetAttribute(gemm2_mma, cudaFuncAttributeMaxDynamicSharedMemorySize, GEMM2_DYN);
        attr_done = true;
    }

    detect_kernel<<<1, 1>>>(ia, ib);
    convert_w<<<(FW * KFLAT / 4 + 255) / 256, 256>>>(W);
    convert_ftab<<<(NUM_FILLERS * FD / 4 + 255) / 256, 256>>>(ftab);
    convert_rtab<<<(NUM_ROLES * RD / 4 + 255) / 256, 256>>>(rtab);

    outer_tc<<<BATCH, 256, OUTER_DYN>>>(ia, ib);

    dim3 grid2(BATCH / 128, FW / 64, KSPLIT);
    gemm2_mma<<<grid2, 256, GEMM2_DYN>>>();

    reduce_kernel<<<(BATCH * FW + 255) / 256, 256>>>(bias, out);
}

// round 11
// speedup vs baseline: 2.2456x; 1.1295x over previous
#include <cuda_runtime.h>
#include <cuda_bf16.h>
#include <cstdint>

// Problem constants
#define BATCH 512
#define SEQ 512
#define FD 128
#define RD 64
#define FW 768
#define KFLAT (FD*RD)   // 8192
#define KSPLIT 8
#define KCHUNK (KFLAT/KSPLIT)  // 1024
#define NUM_FILLERS 50257
#define NUM_ROLES 512

// Scratch (device globals)
__device__ __nv_bfloat16 g_f_hi[(size_t)NUM_FILLERS * FD];
__device__ __nv_bfloat16 g_f_lo[(size_t)NUM_FILLERS * FD];
__device__ __nv_bfloat16 g_r_hi[(size_t)NUM_ROLES * RD];
__device__ __nv_bfloat16 g_r_lo[(size_t)NUM_ROLES * RD];
__device__ __nv_bfloat16 g_a_hi[(size_t)BATCH * KFLAT];
__device__ __nv_bfloat16 g_a_lo[(size_t)BATCH * KFLAT];
__device__ __nv_bfloat16 g_w_hi[(size_t)FW * KFLAT];
__device__ __nv_bfloat16 g_w_lo[(size_t)FW * KFLAT];
__device__ float g_partial[(size_t)KSPLIT * BATCH * FW];
__device__ int   g_flags[2];

__device__ __forceinline__ uint32_t smem_u32(const void* p) {
    uint32_t a;
    asm("{ .reg .u64 t; cvta.to.shared.u64 t, %1; cvt.u32.u64 %0, t; }" : "=r"(a) : "l"(p));
    return a;
}

// ---- cp.async helpers -----------------------------------------------------
#define CP_ASYNC16(dst, src) \
    asm volatile("cp.async.cg.shared.global [%0], [%1], 16;" :: "r"(dst), "l"(src))
#define CP_COMMIT() asm volatile("cp.async.commit_group;" ::: "memory")
#define CP_WAIT(N)  asm volatile("cp.async.wait_group %0;" :: "n"(N) : "memory")

// ---- warp mma helpers -----------------------------------------------------
#define LDSM4(r, addr) \
    asm volatile("ldmatrix.sync.aligned.m8n8.x4.shared.b16 {%0,%1,%2,%3}, [%4];" \
        : "=r"((r)[0]), "=r"((r)[1]), "=r"((r)[2]), "=r"((r)[3]) : "r"(addr))

#define LDSM4T(r, addr) \
    asm volatile("ldmatrix.sync.aligned.m8n8.x4.trans.shared.b16 {%0,%1,%2,%3}, [%4];" \
        : "=r"((r)[0]), "=r"((r)[1]), "=r"((r)[2]), "=r"((r)[3]) : "r"(addr))

#define MMA16816(d, a, b0, b1) \
    asm volatile("mma.sync.aligned.m16n8k16.row.col.f32.bf16.bf16.f32 " \
        "{%0,%1,%2,%3}, {%4,%5,%6,%7}, {%8,%9}, {%0,%1,%2,%3};" \
        : "+f"((d)[0]), "+f"((d)[1]), "+f"((d)[2]), "+f"((d)[3]) \
        : "r"((a)[0]), "r"((a)[1]), "r"((a)[2]), "r"((a)[3]), "r"(b0), "r"(b1))

__device__ __forceinline__ void bf16_split4(float4 v, uint2& h, uint2& l) {
    __nv_bfloat16 h0 = __float2bfloat16(v.x), h1 = __float2bfloat16(v.y);
    __nv_bfloat16 h2 = __float2bfloat16(v.z), h3 = __float2bfloat16(v.w);
    __nv_bfloat162 hp0{h0, h1}, hp1{h2, h3};
    __nv_bfloat162 lp0{__float2bfloat16(v.x - __bfloat162float(h0)),
                       __float2bfloat16(v.y - __bfloat162float(h1))};
    __nv_bfloat162 lp1{__float2bfloat16(v.z - __bfloat162float(h2)),
                       __float2bfloat16(v.w - __bfloat162float(h3))};
    h.x = *(unsigned*)&hp0; h.y = *(unsigned*)&hp1;
    l.x = *(unsigned*)&lp0; l.y = *(unsigned*)&lp1;
}
__device__ __forceinline__ void bf16_split2(float a, float b, unsigned& h, unsigned& l) {
    __nv_bfloat16 h0 = __float2bfloat16(a), h1 = __float2bfloat16(b);
    __nv_bfloat162 hp{h0, h1};
    __nv_bfloat162 lp{__float2bfloat16(a - __bfloat162float(h0)),
                      __float2bfloat16(b - __bfloat162float(h1))};
    h = *(unsigned*)&hp; l = *(unsigned*)&lp;
}

// ---------------------------------------------------------------------------
// Kernel 0: input disambiguation
// ---------------------------------------------------------------------------
__global__ void detect_kernel(const int* __restrict__ a, const int* __restrict__ b)
{
    if (threadIdx.x != 0 || blockIdx.x != 0) return;
    int odd = 0;
#pragma unroll 8
    for (int i = 0; i < 256; i++) odd |= a[2 * i + 1];
    const int is64 = (odd == 0) ? 1 : 0;
    const int s = is64 ? 2 : 1;
    int amax = 0, bmax = 0;
#pragma unroll 8
    for (int i = 0; i < 256; i++) {
        amax = max(amax, a[i * s]);
        bmax = max(bmax, b[i * s]);
    }
    g_flags[0] = (amax < NUM_ROLES && bmax >= NUM_ROLES) ? 1 : 0;
    g_flags[1] = is64;
}

// ---------------------------------------------------------------------------
// One-shot fp32 -> bf16 hi/lo converter (W + filler table + role table fused)
// ---------------------------------------------------------------------------
#define W4   ((size_t)FW * KFLAT / 4)              // 1572864 -> 6144 blocks
#define F4   ((size_t)NUM_FILLERS * FD / 4)        // 1608224 -> 6283 blocks
#define R4   ((size_t)NUM_ROLES * RD / 4)          // 8192    -> 32 blocks
#define W_BLK  6144
#define F_BLK  6283
#define R_BLK  32
__global__ __launch_bounds__(256) void convert_all(
    const float* __restrict__ W, const float* __restrict__ FT,
    const float* __restrict__ RT)
{
    const int bx = blockIdx.x;
    const float* src;
    __nv_bfloat16 *dh, *dl;
    size_t i, n;
    if (bx < W_BLK) {
        i = (size_t)bx * 256 + threadIdx.x; n = W4;
        src = W; dh = g_w_hi; dl = g_w_lo;
    } else if (bx < W_BLK + F_BLK) {
        i = (size_t)(bx - W_BLK) * 256 + threadIdx.x; n = F4;
        src = FT; dh = g_f_hi; dl = g_f_lo;
    } else {
        i = (size_t)(bx - W_BLK - F_BLK) * 256 + threadIdx.x; n = R4;
        src = RT; dh = g_r_hi; dl = g_r_lo;
    }
    if (i >= n) return;
    float4 v = ((const float4*)src)[i];
    uint2 h, l;
    bf16_split4(v, h, l);
    ((uint2*)dh)[i] = h;
    ((uint2*)dl)[i] = l;
}

// ---------------------------------------------------------------------------
// Kernel 1: tensorized outer products, cp.async double-buffered gathers.
//   outer[b] = fe^T @ re : M=128 x N=64 x K=512, bf16 3-pass, fp32 accum.
// grid = 512, 128 threads (4 warps, M split 4x32), warp tile 32(M) x 64(N).
// ---------------------------------------------------------------------------
#define FE_PITCHB 272
#define RE_PITCHB 144
#define O_FEH 0
#define O_FEL 8704
#define O_REH 17408
#define O_REL 22016
#define O_STAGE 26624
#define OUTER_DYN (2 * O_STAGE)
#define O_NT (SEQ / 32)   // 16

__global__ __launch_bounds__(128) void outer_tc(
    const int* __restrict__ ia, const int* __restrict__ ib)
{
    extern __shared__ char dsm[];
    __shared__ int sf[SEQ], sr[SEQ];

    const int b    = blockIdx.x;
    const int tid  = threadIdx.x;
    const int lane = tid & 31;
    const int wid  = tid >> 5;      // 0..3
    const int wm   = wid * 32;      // M offset; N covered fully (64)

    const int swap = g_flags[0];
    const int strd = g_flags[1] ? 2 : 1;
    const int* __restrict__ fidx = swap ? ib : ia;
    const int* __restrict__ ridx = swap ? ia : ib;

    for (int i = tid; i < SEQ; i += 128) {
        size_t e = (size_t)b * SEQ + i;
        sf[i] = min(max(fidx[e * strd], 0), NUM_FILLERS - 1);
        sr[i] = min(max(ridx[e * strd], 0), NUM_ROLES - 1);
    }
    __syncthreads();

    const uint32_t smb = smem_u32(dsm);

    const int fr = tid >> 4, fc = tid & 15;   // fe: 4 rows/thread/variant
    const int rr = tid >> 3, rc = tid & 7;    // re: 2 rows/thread/variant

    auto issue_tile = [&](int kt, int st) {
        const int k0 = kt * 32;
        const uint32_t base = smb + st * O_STAGE;
#pragma unroll
        for (int u = 0; u < 4; u++) {
            int row = fr + u * 8;
            uint32_t d = base + row * FE_PITCHB + fc * 16;
            size_t s = (size_t)sf[k0 + row] * FD + fc * 8;
            CP_ASYNC16(d + O_FEH, g_f_hi + s);
            CP_ASYNC16(d + O_FEL, g_f_lo + s);
        }
#pragma unroll
        for (int u = 0; u < 2; u++) {
            int row = rr + u * 16;
            uint32_t d = base + row * RE_PITCHB + rc * 16;
            size_t s = (size_t)sr[k0 + row] * RD + rc * 8;
            CP_ASYNC16(d + O_REH, g_r_hi + s);
            CP_ASYNC16(d + O_REL, g_r_lo + s);
        }
        CP_COMMIT();
    };

    // trans-ldmatrix lane offsets
    const uint32_t aoff = (uint32_t)((lane & 7) + ((lane >> 4) & 1) * 8) * FE_PITCHB
                        + (uint32_t)(wm + ((lane >> 3) & 1) * 8) * 2;
    const uint32_t boff = (uint32_t)((lane & 7) + ((lane >> 3) & 1) * 8) * RE_PITCHB
                        + (uint32_t)(((lane >> 4) & 1) * 8) * 2;

    float acc[2][8][4];   // [mi][n16*2+h][4]
#pragma unroll
    for (int i = 0; i < 2; i++)
#pragma unroll
        for (int j = 0; j < 8; j++)
#pragma unroll
            for (int q = 0; q < 4; q++) acc[i][j][q] = 0.f;

    issue_tile(0, 0);

    for (int kt = 0; kt < O_NT; kt++) {
        const int st = kt & 1;
        if (kt + 1 < O_NT) { issue_tile(kt + 1, st ^ 1); CP_WAIT(1); }
        else               { CP_WAIT(0); }
        __syncthreads();

        const uint32_t base = smb + st * O_STAGE;
#pragma unroll
        for (int s = 0; s < 2; s++) {
            const uint32_t arow  = base + O_FEH + aoff + (uint32_t)(s * 16) * FE_PITCHB;
            const uint32_t alrow = arow + (O_FEL - O_FEH);
            const uint32_t brow  = base + O_REH + boff + (uint32_t)(s * 16) * RE_PITCHB;
            const uint32_t blrow = brow + (O_REL - O_REH);
            uint32_t ah[2][4], al[2][4];
#pragma unroll
            for (int mi = 0; mi < 2; mi++) {
                LDSM4T(ah[mi], arow + mi * 32);
                LDSM4T(al[mi], alrow + mi * 32);
            }
            uint32_t bh[4][4], bl[4][4];
#pragma unroll
            for (int n16 = 0; n16 < 4; n16++) {
                LDSM4T(bh[n16], brow + n16 * 32);
                LDSM4T(bl[n16], blrow + n16 * 32);
            }
#pragma unroll
            for (int mi = 0; mi < 2; mi++)
#pragma unroll
                for (int n16 = 0; n16 < 4; n16++)
#pragma unroll
                    for (int h = 0; h < 2; h++) {
                        float* d = acc[mi][n16 * 2 + h];
                        MMA16816(d, ah[mi], bh[n16][h * 2], bh[n16][h * 2 + 1]);
                        MMA16816(d, ah[mi], bl[n16][h * 2], bl[n16][h * 2 + 1]);
                        MMA16816(d, al[mi], bh[n16][h * 2], bh[n16][h * 2 + 1]);
                    }
        }
        __syncthreads();
    }

    const int rrow = lane >> 2, rcol = (lane & 3) * 2;
#pragma unroll
    for (int mi = 0; mi < 2; mi++)
#pragma unroll
        for (int nj = 0; nj < 8; nj++) {
            float* d = acc[mi][nj];
            int m = wm + mi * 16 + rrow;
            int n = nj * 8 + rcol;
            size_t off = (size_t)b * KFLAT + (size_t)m * RD + n;
            unsigned h, l;
            bf16_split2(d[0], d[1], h, l);
            *(unsigned*)(g_a_hi + off) = h;
            *(unsigned*)(g_a_lo + off) = l;
            bf16_split2(d[2], d[3], h, l);
            *(unsigned*)(g_a_hi + off + 8 * RD) = h;
            *(unsigned*)(g_a_lo + off + 8 * RD) = l;
        }
}

// ---------------------------------------------------------------------------
// Kernel 2: warp-mma split-K GEMM, cp.async double-buffered.
// grid = (4, 12, KSPLIT), 128 threads (4 warps, M split 4x32),
// warp tile 32(M) x 64(N), CTA 128x64, K-tile 32.
// ---------------------------------------------------------------------------
#define PITCHB 80
#define G_AH 0
#define G_AL 10240
#define G_BH 20480
#define G_BL 25600
#define G_STAGE 30720
#define GEMM2_DYN (2 * G_STAGE)
#define G_NT (KCHUNK / 32)   // 32

__global__ __launch_bounds__(128) void gemm2_mma()
{
    extern __shared__ char dsm[];
    const int tid  = threadIdx.x;
    const int lane = tid & 31;
    const int wid  = tid >> 5;      // 0..3
    const int wm   = wid * 32;

    const int mtile = blockIdx.x, ntile = blockIdx.y, ks = blockIdx.z;
    const size_t arow0 = (size_t)(mtile * 128) * KFLAT;
    const size_t brow0 = (size_t)(ntile * 64) * KFLAT;
    const int kbase = ks * KCHUNK;

    const uint32_t smb = smem_u32(dsm);
    const int row = tid >> 2, c = tid & 3;   // row 0..31

    auto issue_tile = [&](int it, int st) {
        const int kg = kbase + it * 32;
        const uint32_t base = smb + st * G_STAGE;
#pragma unroll
        for (int u = 0; u < 4; u++) {
            int r2 = row + u * 32;
            uint32_t d = base + r2 * PITCHB + c * 16;
            size_t s = arow0 + (size_t)r2 * KFLAT + kg + c * 8;
            CP_ASYNC16(d + G_AH, g_a_hi + s);
            CP_ASYNC16(d + G_AL, g_a_lo + s);
        }
#pragma unroll
        for (int u = 0; u < 2; u++) {
            int r2 = row + u * 32;
            uint32_t d = base + r2 * PITCHB + c * 16;
            size_t s = brow0 + (size_t)r2 * KFLAT + kg + c * 8;
            CP_ASYNC16(d + G_BH, g_w_hi + s);
            CP_ASYNC16(d + G_BL, g_w_lo + s);
        }
        CP_COMMIT();
    };

    const uint32_t a_off0 = (uint32_t)(wm + (lane & 15)) * PITCHB + ((lane >> 4) << 4);
    const uint32_t b_off0 = (uint32_t)(((lane >> 4) << 3) + (lane & 7)) * PITCHB
                          + (((lane >> 3) & 1) << 4);

    float acc[2][8][4];
#pragma unroll
    for (int i = 0; i < 2; i++)
#pragma unroll
        for (int j = 0; j < 8; j++)
#pragma unroll
            for (int q = 0; q < 4; q++) acc[i][j][q] = 0.f;

    issue_tile(0, 0);

    for (int it = 0; it < G_NT; it++) {
        const int st = it & 1;
        if (it + 1 < G_NT) { issue_tile(it + 1, st ^ 1); CP_WAIT(1); }
        else               { CP_WAIT(0); }
        __syncthreads();

        const uint32_t base = smb + st * G_STAGE;
#pragma unroll
        for (int s = 0; s < 2; s++) {
            const uint32_t koff = s * 32;
            uint32_t ah[2][4], al[2][4];
#pragma unroll
            for (int i = 0; i < 2; i++) {
                uint32_t off = a_off0 + (uint32_t)(i * 16) * PITCHB + koff;
                LDSM4(ah[i], base + G_AH + off);
                LDSM4(al[i], base + G_AL + off);
            }
            uint32_t bh[4][4], bl[4][4];
#pragma unroll
            for (int j = 0; j < 4; j++) {
                uint32_t off = b_off0 + (uint32_t)(j * 16) * PITCHB + koff;
                LDSM4(bh[j], base + G_BH + off);
                LDSM4(bl[j], base + G_BL + off);
            }
#pragma unroll
            for (int i = 0; i < 2; i++)
#pragma unroll
                for (int j = 0; j < 4; j++)
#pragma unroll
                    for (int h = 0; h < 2; h++) {
                        float* d = acc[i][j * 2 + h];
                        MMA16816(d, ah[i], bh[j][h * 2], bh[j][h * 2 + 1]);
                        MMA16816(d, ah[i], bl[j][h * 2], bl[j][h * 2 + 1]);
                        MMA16816(d, al[i], bh[j][h * 2], bh[j][h * 2 + 1]);
                    }
        }
        __syncthreads();
    }

    const int rbase = mtile * 128 + wm + (lane >> 2);
    const int cbase = ntile * 64 + (lane & 3) * 2;
    float* P = g_partial + (size_t)ks * BATCH * FW;
#pragma unroll
    for (int i = 0; i < 2; i++)
#pragma unroll
        for (int nj = 0; nj < 8; nj++) {
            float* d = acc[i][nj];
            size_t r0 = (size_t)(rbase + i * 16) * FW + cbase + nj * 8;
            *(float2*)&P[r0]          = make_float2(d[0], d[1]);
            *(float2*)&P[r0 + 8 * FW] = make_float2(d[2], d[3]);
        }
}

// ---------------------------------------------------------------------------
// Kernel 3: reduce split-K partials + bias -> out[1][B][FW]
// ---------------------------------------------------------------------------
__global__ void reduce_kernel(const float* __restrict__ bias, float* __restrict__ out)
{
    int idx = blockIdx.x * 256 + threadIdx.x;
    if (idx < BATCH * FW) {
        int n = idx % FW;
        float s = bias[n];
#pragma unroll
        for (int ks = 0; ks < KSPLIT; ks++)
            s += g_partial[(size_t)ks * BATCH * FW + idx];
        out[idx] = s;
    }
}

// ---------------------------------------------------------------------------
extern "C" void kernel_launch(void* const* d_in, const int* in_sizes, int n_in,
                              void* d_out, int out_size)
{
    const void* idx_arr[2] = {nullptr, nullptr};
    int n_idx = 0;
    const float* ftab = nullptr;
    const float* rtab = nullptr;
    const float* W    = nullptr;
    const float* bias = nullptr;

    for (int i = 0; i < n_in; i++) {
        switch (in_sizes[i]) {
            case BATCH * SEQ:
                if (n_idx < 2) idx_arr[n_idx++] = d_in[i];
                break;
            case NUM_FILLERS * FD: ftab = (const float*)d_in[i]; break;
            case NUM_ROLES * RD:   rtab = (const float*)d_in[i]; break;
            case FW * KFLAT:       W    = (const float*)d_in[i]; break;
            case FW:               bias = (const float*)d_in[i]; break;
            default: break;
        }
    }

    const int* ia = (const int*)idx_arr[0];
    const int* ib = (const int*)idx_arr[1];
    float* out = (float*)d_out;

    static bool attr_done = false;
    if (!attr_done) {
        cudaFuncSetAttribute(outer_tc, cudaFuncAttributeMaxDynamicSharedMemorySize, OUTER_DYN);
        cudaFuncSetAttribute(gemm2_mma, cudaFuncAttributeMaxDynamicSharedMemorySize, GEMM2_DYN);
        attr_done = true;
    }

    detect_kernel<<<1, 1>>>(ia, ib);
    convert_all<<<W_BLK + F_BLK + R_BLK, 256>>>(W, ftab, rtab);

    outer_tc<<<BATCH, 128, OUTER_DYN>>>(ia, ib);

    dim3 grid2(BATCH / 128, FW / 64, KSPLIT);
    gemm2_mma<<<grid2, 128, GEMM2_DYN>>>();

    reduce_kernel<<<(BATCH * FW + 255) / 256, 256>>>(bias, out);
}